// round 14
// baseline (speedup 1.0000x reference)
#include <cuda_runtime.h>
#include <math.h>

#define BATCH   16
#define N_PEP   128
#define M_PRO   2048
#define HEADS   8
#define DH      96
#define INNER   768
#define SCALE_F 0.10206207261596577f   /* 96^-0.5 */
#define NEG_F   -1000000.0f
#define EPS_F   1e-5f

#define BM 128
#define BN 128
#define BK 16
#define TILE_W 2048
#define STAGES 3
#define KSPLIT 4
#define KCHUNK (M_PRO / KSPLIT)   /* 512 */

// ---------------- scratch (device globals; no allocations) ----------------
__device__ float g_q   [BATCH * N_PEP * INNER];
__device__ float g_k   [BATCH * M_PRO * INNER];
__device__ float g_vp  [BATCH * M_PRO * INNER];
__device__ float g_vq  [BATCH * N_PEP * INNER];
__device__ float g_cp  [BATCH * N_PEP * INNER];
__device__ float g_cq  [BATCH * M_PRO * INNER];
__device__ float g_y1  [BATCH * N_PEP * INNER];
__device__ float g_y2  [BATCH * M_PRO * INNER];
__device__ float g_part[KSPLIT * BATCH * N_PEP * INNER];

// ---------------- helpers ----------------
__device__ __forceinline__ void mma_tf32(float* c, const unsigned* a,
                                         unsigned b0, unsigned b1) {
    asm volatile(
        "mma.sync.aligned.m16n8k8.row.col.f32.tf32.tf32.f32 "
        "{%0,%1,%2,%3}, {%4,%5,%6,%7}, {%8,%9}, {%0,%1,%2,%3};"
        : "+f"(c[0]), "+f"(c[1]), "+f"(c[2]), "+f"(c[3])
        : "r"(a[0]), "r"(a[1]), "r"(a[2]), "r"(a[3]), "r"(b0), "r"(b1));
}

__device__ __forceinline__ void cpasync16(unsigned* dst, const float* src, bool pred) {
    unsigned sa = (unsigned)__cvta_generic_to_shared(dst);
    int sz = pred ? 16 : 0;
    asm volatile("cp.async.cg.shared.global [%0], [%1], 16, %2;\n"
                 :: "r"(sa), "l"(src), "r"(sz));
}
#define CP_COMMIT() asm volatile("cp.async.commit_group;\n" ::)
#define CP_WAIT1()  asm volatile("cp.async.wait_group 1;\n" ::)
#define CP_WAIT0()  asm volatile("cp.async.wait_group 0;\n" ::)

// swizzled word layouts, zero padding, all accesses conflict-free:
#define SW16(r, c)  ((r) * 16  + ((c) ^ ((((r) >> 1) & 3) * 4)))
#define SW128(r, c) ((r) * 128 + ((c) ^ (((r) & 7) * 8)))

// ---------------- 128x128x16 3-stage-pipelined tf32 GEMM tile ----------------
// Raw fp32 bits fed to mma.sync.tf32 (HW truncates).
// TA: A stored (K, M) row-major, lda; else (M, K).
// TB: B stored (N, K) row-major, ldb; else (K, N).
// MASK: apply attention masks in epilogue.
template <bool TA, bool TB, bool MASK>
__device__ __forceinline__ void gemm_mma(const float* __restrict__ A,
                                         const float* __restrict__ Bm,
                                         float* __restrict__ C,
                                         int M, int N, int K,
                                         int lda, int ldb, int ldc,
                                         float alpha, int row0, int col0,
                                         const int* __restrict__ rowmask,
                                         const int* __restrict__ colmask)
{
    __shared__ unsigned sAb[STAGES][TILE_W];
    __shared__ unsigned sBb[STAGES][TILE_W];

    const int tid  = threadIdx.x;
    const int lane = tid & 31;
    const int wid  = tid >> 5;
    const int wm   = (wid >> 1) * 32;
    const int wn   = (wid & 1) * 64;

    // number of live j-steps for this warp (each j covers 8 output columns)
    int jcap = (N - col0 - wn + 7) >> 3;
    if (jcap > 8) jcap = 8;
    if (jcap < 0) jcap = 0;

    float acc[2][8][4];
#pragma unroll
    for (int i = 0; i < 2; i++)
#pragma unroll
        for (int j = 0; j < 8; j++)
#pragma unroll
            for (int t = 0; t < 4; t++) acc[i][j][t] = 0.0f;

    const int nTiles = K / BK;

    auto issue = [&](int buf, int k0) {
        unsigned* sA = sAb[buf];
        unsigned* sB = sBb[buf];
#pragma unroll
        for (int it = 0; it < 2; it++) {
            int idx = tid + it * 256;
            if (!TA) {
                int m  = idx >> 2;
                int kk = (idx & 3) * 4;
                cpasync16(&sA[SW16(m, kk)],
                          &A[(long)(row0 + m) * lda + k0 + kk], true);
            } else {
                int kk = idx >> 5;
                int m4 = (idx & 31) * 4;
                cpasync16(&sA[SW128(kk, m4)],
                          &A[(long)(k0 + kk) * lda + row0 + m4], true);
            }
        }
#pragma unroll
        for (int it = 0; it < 2; it++) {
            int idx = tid + it * 256;
            if (!TB) {
                int kk = idx >> 5;
                int n4 = (idx & 31) * 4;
                cpasync16(&sB[SW128(kk, n4)],
                          &Bm[(long)(k0 + kk) * ldb + col0 + n4],
                          col0 + n4 < N);
            } else {
                int n  = idx >> 2;
                int kq = (idx & 3) * 4;
                cpasync16(&sB[SW16(n, kq)],
                          &Bm[(long)(col0 + n) * ldb + k0 + kq],
                          col0 + n < N);
            }
        }
        CP_COMMIT();
    };

    const int arq = lane >> 2;
    const int ac  = lane & 3;

    issue(0, 0);
    if (nTiles > 1) issue(1, BK);

    for (int t = 0; t < nTiles; t++) {
        const int buf = t % STAGES;
        unsigned* sA = sAb[buf];
        unsigned* sB = sBb[buf];

        if (t + 1 < nTiles) CP_WAIT1(); else CP_WAIT0();
        __syncthreads();
        if (t + 2 < nTiles) issue((t + 2) % STAGES, (t + 2) * BK);

#pragma unroll
        for (int kc = 0; kc < BK; kc += 8) {
            unsigned af0[4], af1[4];
            if (!TA) {
                af0[0] = sA[SW16(wm + arq,      kc + ac)];
                af0[1] = sA[SW16(wm + arq + 8,  kc + ac)];
                af0[2] = sA[SW16(wm + arq,      kc + ac + 4)];
                af0[3] = sA[SW16(wm + arq + 8,  kc + ac + 4)];
                af1[0] = sA[SW16(wm + arq + 16, kc + ac)];
                af1[1] = sA[SW16(wm + arq + 24, kc + ac)];
                af1[2] = sA[SW16(wm + arq + 16, kc + ac + 4)];
                af1[3] = sA[SW16(wm + arq + 24, kc + ac + 4)];
            } else {
                af0[0] = sA[SW128(kc + ac,     wm + arq)];
                af0[1] = sA[SW128(kc + ac,     wm + arq + 8)];
                af0[2] = sA[SW128(kc + ac + 4, wm + arq)];
                af0[3] = sA[SW128(kc + ac + 4, wm + arq + 8)];
                af1[0] = sA[SW128(kc + ac,     wm + arq + 16)];
                af1[1] = sA[SW128(kc + ac,     wm + arq + 24)];
                af1[2] = sA[SW128(kc + ac + 4, wm + arq + 16)];
                af1[3] = sA[SW128(kc + ac + 4, wm + arq + 24)];
            }
#pragma unroll
            for (int j = 0; j < 8; j++) {
                if (j >= jcap) break;          // uniform per warp: skip dead columns
                const int bn = wn + j * 8 + arq;
                unsigned b0, b1;
                if (!TB) {
                    b0 = sB[SW128(kc + ac,     bn)];
                    b1 = sB[SW128(kc + ac + 4, bn)];
                } else {
                    b0 = sB[SW16(bn, kc + ac)];
                    b1 = sB[SW16(bn, kc + ac + 4)];
                }
                mma_tf32(acc[0][j], af0, b0, b1);
                mma_tf32(acc[1][j], af1, b0, b1);
            }
        }
    }

    // ---- epilogue ----
#pragma unroll
    for (int i = 0; i < 2; i++) {
        int r  = row0 + wm + i * 16 + arq;
        int rv0 = 1, rv1 = 1;
        if (MASK) { rv0 = rowmask[r]; rv1 = rowmask[r + 8]; }
#pragma unroll
        for (int j = 0; j < 8; j++) {
            int c = col0 + wn + j * 8 + ac * 2;
            if (c < N) {
                float v0 = alpha * acc[i][j][0];
                float v1 = alpha * acc[i][j][1];
                float v2 = alpha * acc[i][j][2];
                float v3 = alpha * acc[i][j][3];
                if (MASK) {
                    int cm0 = colmask[c], cm1 = colmask[c + 1];
                    if (rv0 == 0 || cm0 == 0) v0 = NEG_F;
                    if (rv0 == 0 || cm1 == 0) v1 = NEG_F;
                    if (rv1 == 0 || cm0 == 0) v2 = NEG_F;
                    if (rv1 == 0 || cm1 == 0) v3 = NEG_F;
                }
                *(float2*)&C[(long)r * ldc + c]       = make_float2(v0, v1);
                *(float2*)&C[(long)(r + 8) * ldc + c] = make_float2(v2, v3);
            }
        }
    }
}

// ---------------- fused projection mega-kernel ----------------
// grid (6, 544): by<16 -> q, by<32 -> vq, by<288 -> k, else vp
__global__ void __launch_bounds__(256, 2)
k_proj_all(const float* __restrict__ pep, const float* __restrict__ prot,
           const float* __restrict__ Wq,  const float* __restrict__ Wvq,
           const float* __restrict__ Wk,  const float* __restrict__ Wvp,
           float* __restrict__ q, float* __restrict__ vq,
           float* __restrict__ k, float* __restrict__ vp)
{
    int by = blockIdx.y;
    const float *A, *Bm; float* C; int row0;
    if (by < 16)        { A = pep;  Bm = Wq;  C = q;  row0 = by * BM; }
    else if (by < 32)   { A = pep;  Bm = Wvq; C = vq; row0 = (by - 32 + 16) * BM; }
    else if (by < 288)  { A = prot; Bm = Wk;  C = k;  row0 = (by - 32) * BM; }
    else                { A = prot; Bm = Wvp; C = vp; row0 = (by - 288) * BM; }
    gemm_mma<false, false, false>(A, Bm, C, 0, INNER, INNER,
                                  INNER, INNER, INNER, 1.0f,
                                  row0, blockIdx.x * BN, 0, 0);
}

// scores with fused masking: writes NEG_F where masked
__global__ void __launch_bounds__(256, 2)
k_scores(const float* __restrict__ q, const float* __restrict__ kb,
         float* __restrict__ attn,
         const int* __restrict__ pmask, const int* __restrict__ promask)
{
    int z = blockIdx.z;
    int b = z >> 3, h = z & 7;
    const float* A  = q  + (long)b * N_PEP * INNER + h * DH;
    const float* Bm = kb + (long)b * M_PRO * INNER + h * DH;
    float* C = attn + (long)z * N_PEP * M_PRO;
    gemm_mma<false, true, true>(A, Bm, C, N_PEP, M_PRO, DH,
                                INNER, INNER, M_PRO, SCALE_F,
                                blockIdx.y * BM, blockIdx.x * BN,
                                pmask + b * N_PEP, promask + b * M_PRO);
}

// fused context mega-kernel: z<512 -> ctxprot split-K chunk; z>=512 -> ctxpep tile
__global__ void __launch_bounds__(256, 2)
k_ctx_all(const float* __restrict__ attn, const float* __restrict__ vp,
          const float* __restrict__ vq, float* __restrict__ part,
          float* __restrict__ cq)
{
    int z = blockIdx.z;
    if (z < BATCH * HEADS * KSPLIT) {
        int bh = z >> 2, chunk = z & 3;
        int b = bh >> 3, h = bh & 7;
        const float* A  = attn + (long)bh * N_PEP * M_PRO + chunk * KCHUNK;
        const float* Bm = vp + (long)b * M_PRO * INNER + (long)chunk * KCHUNK * INNER + h * DH;
        float* C = part + (long)chunk * (BATCH * N_PEP * INNER)
                        + (long)b * N_PEP * INNER + h * DH;
        gemm_mma<false, false, false>(A, Bm, C, N_PEP, DH, KCHUNK,
                                      M_PRO, INNER, INNER, 1.0f, 0, 0, 0, 0);
    } else {
        int idx = z - BATCH * HEADS * KSPLIT;    // 0..2047
        int bh = idx >> 4, ry = idx & 15;
        int b = bh >> 3, h = bh & 7;
        const float* A  = attn + (long)bh * N_PEP * M_PRO;   // (K=n, M=m)
        const float* Bm = vq + (long)b * N_PEP * INNER + h * DH;
        float* C = cq + (long)b * M_PRO * INNER + h * DH;
        gemm_mma<true, false, false>(A, Bm, C, M_PRO, DH, N_PEP,
                                     M_PRO, INNER, INNER, 1.0f,
                                     ry * BM, 0, 0, 0);
    }
}

// reduce 4 partials -> cp
__global__ void __launch_bounds__(256)
k_reduce4(const float* __restrict__ part, float* __restrict__ cp)
{
    const long STRIDE = (long)BATCH * N_PEP * INNER;
    long i = ((long)blockIdx.x * 256 + threadIdx.x) * 4;
    if (i >= STRIDE) return;
    float4 a = *(const float4*)&part[i];
    float4 b = *(const float4*)&part[STRIDE + i];
    float4 c = *(const float4*)&part[2 * STRIDE + i];
    float4 d = *(const float4*)&part[3 * STRIDE + i];
    *(float4*)&cp[i] = make_float4(a.x + b.x + c.x + d.x, a.y + b.y + c.y + d.y,
                                   a.z + b.z + c.z + d.z, a.w + b.w + c.w + d.w);
}

// fused output projections: by<256 -> y2 (cq@Woq), else -> y1 (cp@Wop)
__global__ void __launch_bounds__(256, 2)
k_out_dual(const float* __restrict__ cq, const float* __restrict__ Woq,
           float* __restrict__ y2,
           const float* __restrict__ cp, const float* __restrict__ Wop,
           float* __restrict__ y1)
{
    if (blockIdx.y < 256) {
        gemm_mma<false, false, false>(cq, Woq, y2, BATCH * M_PRO, INNER, INNER,
                                      INNER, INNER, INNER, 1.0f,
                                      blockIdx.y * BM, blockIdx.x * BN, 0, 0);
    } else {
        gemm_mma<false, false, false>(cp, Wop, y1, BATCH * N_PEP, INNER, INNER,
                                      INNER, INNER, INNER, 1.0f,
                                      (blockIdx.y - 256) * BM, blockIdx.x * BN, 0, 0);
    }
}

// ---------------- softmax (masks pre-applied as NEG_F) ----------------
__global__ void __launch_bounds__(256)
k_softmax(float* __restrict__ attn)
{
    const int tid = threadIdx.x;
    float* p = attn + (long)blockIdx.x * M_PRO;

    float4 v0 = *(float4*)&p[tid * 4];
    float4 v1 = *(float4*)&p[1024 + tid * 4];

    float mx = fmaxf(fmaxf(fmaxf(v0.x, v0.y), fmaxf(v0.z, v0.w)),
                     fmaxf(fmaxf(v1.x, v1.y), fmaxf(v1.z, v1.w)));
#pragma unroll
    for (int o = 16; o; o >>= 1)
        mx = fmaxf(mx, __shfl_xor_sync(0xffffffff, mx, o));
    __shared__ float red[8];
    if ((tid & 31) == 0) red[tid >> 5] = mx;
    __syncthreads();
    if (tid < 8) {
        float m = red[tid];
#pragma unroll
        for (int o = 4; o; o >>= 1) m = fmaxf(m, __shfl_xor_sync(0xff, m, o));
        red[tid] = m;
    }
    __syncthreads();
    mx = red[0];

    v0.x = expf(v0.x - mx); v0.y = expf(v0.y - mx);
    v0.z = expf(v0.z - mx); v0.w = expf(v0.w - mx);
    v1.x = expf(v1.x - mx); v1.y = expf(v1.y - mx);
    v1.z = expf(v1.z - mx); v1.w = expf(v1.w - mx);
    float s = v0.x + v0.y + v0.z + v0.w + v1.x + v1.y + v1.z + v1.w;
#pragma unroll
    for (int o = 16; o; o >>= 1) s += __shfl_xor_sync(0xffffffff, s, o);
    __shared__ float red2[8];
    if ((tid & 31) == 0) red2[tid >> 5] = s;
    __syncthreads();
    if (tid < 8) {
        float t = red2[tid];
#pragma unroll
        for (int o = 4; o; o >>= 1) t += __shfl_xor_sync(0xff, t, o);
        red2[tid] = t;
    }
    __syncthreads();
    float inv = 1.0f / red2[0];

    v0.x *= inv; v0.y *= inv; v0.z *= inv; v0.w *= inv;
    v1.x *= inv; v1.y *= inv; v1.z *= inv; v1.w *= inv;
    *(float4*)&p[tid * 4] = v0;
    *(float4*)&p[1024 + tid * 4] = v1;
}

// ---------------- fused LN ----------------
__global__ void __launch_bounds__(256)
k_ln_dual(const float* __restrict__ y1, const float* __restrict__ bo1,
          const float* __restrict__ res1, float* __restrict__ out1,
          const float* __restrict__ y2, const float* __restrict__ bo2,
          const float* __restrict__ res2, float* __restrict__ out2,
          const float* __restrict__ g, const float* __restrict__ beta)
{
    const int NROW1 = BATCH * N_PEP;   // 2048
    int row = blockIdx.x;
    const float *y, *bo, *r; float* out; int lrow;
    if (row < NROW1) { y = y1; bo = bo1; r = res1; out = out1; lrow = row; }
    else             { y = y2; bo = bo2; r = res2; out = out2; lrow = row - NROW1; }
    int tid = threadIdx.x;
    const float* yp = y + (long)lrow * INNER;
    const float* rp = r + (long)lrow * INNER;

    float x[3];
    float s = 0.0f;
#pragma unroll
    for (int i = 0; i < 3; i++) {
        int c = tid + i * 256;
        x[i] = yp[c] + bo[c] + rp[c];
        s += x[i];
    }
#pragma unroll
    for (int o = 16; o; o >>= 1) s += __shfl_xor_sync(0xffffffff, s, o);
    __shared__ float red[8];
    if ((tid & 31) == 0) red[tid >> 5] = s;
    __syncthreads();
    if (tid < 8) {
        float t = red[tid];
#pragma unroll
        for (int o = 4; o; o >>= 1) t += __shfl_xor_sync(0xff, t, o);
        red[tid] = t;
    }
    __syncthreads();
    float mu = red[0] * (1.0f / INNER);

    float v = 0.0f;
#pragma unroll
    for (int i = 0; i < 3; i++) { float d = x[i] - mu; v += d * d; }
#pragma unroll
    for (int o = 16; o; o >>= 1) v += __shfl_xor_sync(0xffffffff, v, o);
    __shared__ float red2[8];
    if ((tid & 31) == 0) red2[tid >> 5] = v;
    __syncthreads();
    if (tid < 8) {
        float t = red2[tid];
#pragma unroll
        for (int o = 4; o; o >>= 1) t += __shfl_xor_sync(0xff, t, o);
        red2[tid] = t;
    }
    __syncthreads();
    float rstd = rsqrtf(red2[0] * (1.0f / INNER) + EPS_F);
#pragma unroll
    for (int i = 0; i < 3; i++) {
        int c = tid + i * 256;
        out[(long)lrow * INNER + c] = (x[i] - mu) * rstd * g[c] + beta[c];
    }
}

// ---------------- launch ----------------
extern "C" void kernel_launch(void* const* d_in, const int* in_sizes, int n_in,
                              void* d_out, int out_size)
{
    const float* peptide = (const float*)d_in[0];
    const float* protein = (const float*)d_in[1];
    const int*   pmask   = (const int*)  d_in[2];
    const int*   promask = (const int*)  d_in[3];
    const float* Wq      = (const float*)d_in[4];
    const float* Wk      = (const float*)d_in[5];
    const float* Wvp     = (const float*)d_in[6];
    const float* Wvq     = (const float*)d_in[7];
    const float* Wop     = (const float*)d_in[8];
    const float* bop     = (const float*)d_in[9];
    const float* Woq     = (const float*)d_in[10];
    const float* boq     = (const float*)d_in[11];
    const float* lng     = (const float*)d_in[12];
    const float* lnb     = (const float*)d_in[13];

    float* out = (float*)d_out;
    float* out_prot = out;                                   // (16,128,768)
    float* out_pep  = out + (long)BATCH * N_PEP * INNER;     // (16,2048,768)
    float* attn     = out_pep + (long)BATCH * M_PRO * INNER; // (16,8,128,2048)

    float *q, *k, *vp, *vq, *cp, *cq, *y1, *y2, *part;
    cudaGetSymbolAddress((void**)&q,  g_q);
    cudaGetSymbolAddress((void**)&k,  g_k);
    cudaGetSymbolAddress((void**)&vp, g_vp);
    cudaGetSymbolAddress((void**)&vq, g_vq);
    cudaGetSymbolAddress((void**)&cp, g_cp);
    cudaGetSymbolAddress((void**)&cq, g_cq);
    cudaGetSymbolAddress((void**)&y1, g_y1);
    cudaGetSymbolAddress((void**)&y2, g_y2);
    cudaGetSymbolAddress((void**)&part, g_part);

    const dim3 blk(256);

    // all four projections in one launch
    k_proj_all<<<dim3(6, 544), blk>>>(peptide, protein, Wq, Wvq, Wk, Wvp,
                                      q, vq, k, vp);

    // attention scores (mask fused) + softmax (attn lives in d_out)
    k_scores <<<dim3(16, 1, BATCH * HEADS), blk>>>(q, k, attn, pmask, promask);
    k_softmax<<<BATCH * HEADS * N_PEP, 256>>>(attn);

    // both context GEMMs in one launch
    k_ctx_all<<<dim3(1, 1, BATCH * HEADS * KSPLIT + BATCH * HEADS * 16), blk>>>(
        attn, vp, vq, part, cq);
    k_reduce4<<<(BATCH * N_PEP * INNER / 4 + 255) / 256, blk>>>(part, cp);

    // output projections (y2 + y1 fused into one launch)
    k_out_dual<<<dim3(6, 272), blk>>>(cq, Woq, y2, cp, Wop, y1);

    // bias + residual + layernorm (fused)
    k_ln_dual<<<BATCH * N_PEP + BATCH * M_PRO, 256>>>(
        y1, bop, peptide, out_prot, y2, boq, protein, out_pep, lng, lnb);
}

// round 15
// speedup vs baseline: 1.1220x; 1.1220x over previous
#include <cuda_runtime.h>
#include <math.h>

#define BATCH   16
#define N_PEP   128
#define M_PRO   2048
#define HEADS   8
#define DH      96
#define INNER   768
#define SCALE_F 0.10206207261596577f   /* 96^-0.5 */
#define NEG_F   -1000000.0f
#define EPS_F   1e-5f

#define BM 128
#define BN 128
#define BK 16
#define TILE_W 2048
#define STAGES 3
#define KSPLIT 4
#define KCHUNK (M_PRO / KSPLIT)   /* 512 */

// ---------------- scratch (device globals; no allocations) ----------------
__device__ float g_q   [BATCH * N_PEP * INNER];
__device__ float g_k   [BATCH * M_PRO * INNER];
__device__ float g_vp  [BATCH * M_PRO * INNER];
__device__ float g_vq  [BATCH * N_PEP * INNER];
__device__ float g_cp  [BATCH * N_PEP * INNER];
__device__ float g_cq  [BATCH * M_PRO * INNER];
__device__ float g_y1  [BATCH * N_PEP * INNER];
__device__ float g_y2  [BATCH * M_PRO * INNER];
__device__ float g_part[KSPLIT * BATCH * N_PEP * INNER];

// ---------------- helpers ----------------
__device__ __forceinline__ void mma_tf32(float* c, const unsigned* a,
                                         unsigned b0, unsigned b1) {
    asm volatile(
        "mma.sync.aligned.m16n8k8.row.col.f32.tf32.tf32.f32 "
        "{%0,%1,%2,%3}, {%4,%5,%6,%7}, {%8,%9}, {%0,%1,%2,%3};"
        : "+f"(c[0]), "+f"(c[1]), "+f"(c[2]), "+f"(c[3])
        : "r"(a[0]), "r"(a[1]), "r"(a[2]), "r"(a[3]), "r"(b0), "r"(b1));
}

__device__ __forceinline__ void cpasync16(unsigned* dst, const float* src, bool pred) {
    unsigned sa = (unsigned)__cvta_generic_to_shared(dst);
    int sz = pred ? 16 : 0;
    asm volatile("cp.async.cg.shared.global [%0], [%1], 16, %2;\n"
                 :: "r"(sa), "l"(src), "r"(sz));
}
#define CP_COMMIT() asm volatile("cp.async.commit_group;\n" ::)
#define CP_WAIT1()  asm volatile("cp.async.wait_group 1;\n" ::)
#define CP_WAIT0()  asm volatile("cp.async.wait_group 0;\n" ::)

// swizzled word layouts, zero padding, all accesses conflict-free:
#define SW16(r, c)  ((r) * 16  + ((c) ^ ((((r) >> 1) & 3) * 4)))
#define SW128(r, c) ((r) * 128 + ((c) ^ (((r) & 7) * 8)))

// ---------------- 128x128x16 3-stage-pipelined tf32 GEMM tile ----------------
// Raw fp32 bits fed to mma.sync.tf32 (HW truncates).
// TA: A stored (K, M) row-major, lda; else (M, K).
// TB: B stored (N, K) row-major, ldb; else (K, N).
// MASK: apply attention masks in epilogue.
// TRIM: skip j-steps whose 8-column group is entirely >= N (used ONLY for
//       narrow-N (DH=96) context GEMMs; bulk kernels use TRIM=false which is
//       byte-identical to the proven R12 inner loop).
template <bool TA, bool TB, bool MASK, bool TRIM>
__device__ __forceinline__ void gemm_mma(const float* __restrict__ A,
                                         const float* __restrict__ Bm,
                                         float* __restrict__ C,
                                         int M, int N, int K,
                                         int lda, int ldb, int ldc,
                                         float alpha, int row0, int col0,
                                         const int* __restrict__ rowmask,
                                         const int* __restrict__ colmask)
{
    __shared__ unsigned sAb[STAGES][TILE_W];
    __shared__ unsigned sBb[STAGES][TILE_W];

    const int tid  = threadIdx.x;
    const int lane = tid & 31;
    const int wid  = tid >> 5;
    const int wm   = (wid >> 1) * 32;
    const int wn   = (wid & 1) * 64;

    int jcap = 8;
    if (TRIM) {
        jcap = (N - col0 - wn + 7) >> 3;
        if (jcap > 8) jcap = 8;
        if (jcap < 0) jcap = 0;
    }

    float acc[2][8][4];
#pragma unroll
    for (int i = 0; i < 2; i++)
#pragma unroll
        for (int j = 0; j < 8; j++)
#pragma unroll
            for (int t = 0; t < 4; t++) acc[i][j][t] = 0.0f;

    const int nTiles = K / BK;

    auto issue = [&](int buf, int k0) {
        unsigned* sA = sAb[buf];
        unsigned* sB = sBb[buf];
#pragma unroll
        for (int it = 0; it < 2; it++) {
            int idx = tid + it * 256;
            if (!TA) {
                int m  = idx >> 2;
                int kk = (idx & 3) * 4;
                cpasync16(&sA[SW16(m, kk)],
                          &A[(long)(row0 + m) * lda + k0 + kk], true);
            } else {
                int kk = idx >> 5;
                int m4 = (idx & 31) * 4;
                cpasync16(&sA[SW128(kk, m4)],
                          &A[(long)(k0 + kk) * lda + row0 + m4], true);
            }
        }
#pragma unroll
        for (int it = 0; it < 2; it++) {
            int idx = tid + it * 256;
            if (!TB) {
                int kk = idx >> 5;
                int n4 = (idx & 31) * 4;
                cpasync16(&sB[SW128(kk, n4)],
                          &Bm[(long)(k0 + kk) * ldb + col0 + n4],
                          col0 + n4 < N);
            } else {
                int n  = idx >> 2;
                int kq = (idx & 3) * 4;
                cpasync16(&sB[SW16(n, kq)],
                          &Bm[(long)(col0 + n) * ldb + k0 + kq],
                          col0 + n < N);
            }
        }
        CP_COMMIT();
    };

    const int arq = lane >> 2;
    const int ac  = lane & 3;

    issue(0, 0);
    if (nTiles > 1) issue(1, BK);

    for (int t = 0; t < nTiles; t++) {
        const int buf = t % STAGES;
        unsigned* sA = sAb[buf];
        unsigned* sB = sBb[buf];

        if (t + 1 < nTiles) CP_WAIT1(); else CP_WAIT0();
        __syncthreads();
        if (t + 2 < nTiles) issue((t + 2) % STAGES, (t + 2) * BK);

#pragma unroll
        for (int kc = 0; kc < BK; kc += 8) {
            unsigned af0[4], af1[4];
            if (!TA) {
                af0[0] = sA[SW16(wm + arq,      kc + ac)];
                af0[1] = sA[SW16(wm + arq + 8,  kc + ac)];
                af0[2] = sA[SW16(wm + arq,      kc + ac + 4)];
                af0[3] = sA[SW16(wm + arq + 8,  kc + ac + 4)];
                af1[0] = sA[SW16(wm + arq + 16, kc + ac)];
                af1[1] = sA[SW16(wm + arq + 24, kc + ac)];
                af1[2] = sA[SW16(wm + arq + 16, kc + ac + 4)];
                af1[3] = sA[SW16(wm + arq + 24, kc + ac + 4)];
            } else {
                af0[0] = sA[SW128(kc + ac,     wm + arq)];
                af0[1] = sA[SW128(kc + ac,     wm + arq + 8)];
                af0[2] = sA[SW128(kc + ac + 4, wm + arq)];
                af0[3] = sA[SW128(kc + ac + 4, wm + arq + 8)];
                af1[0] = sA[SW128(kc + ac,     wm + arq + 16)];
                af1[1] = sA[SW128(kc + ac,     wm + arq + 24)];
                af1[2] = sA[SW128(kc + ac + 4, wm + arq + 16)];
                af1[3] = sA[SW128(kc + ac + 4, wm + arq + 24)];
            }
            if (!TRIM) {
#pragma unroll
                for (int j = 0; j < 8; j++) {
                    const int bn = wn + j * 8 + arq;
                    unsigned b0, b1;
                    if (!TB) {
                        b0 = sB[SW128(kc + ac,     bn)];
                        b1 = sB[SW128(kc + ac + 4, bn)];
                    } else {
                        b0 = sB[SW16(bn, kc + ac)];
                        b1 = sB[SW16(bn, kc + ac + 4)];
                    }
                    mma_tf32(acc[0][j], af0, b0, b1);
                    mma_tf32(acc[1][j], af1, b0, b1);
                }
            } else {
                for (int j = 0; j < jcap; j++) {
                    const int bn = wn + j * 8 + arq;
                    unsigned b0, b1;
                    if (!TB) {
                        b0 = sB[SW128(kc + ac,     bn)];
                        b1 = sB[SW128(kc + ac + 4, bn)];
                    } else {
                        b0 = sB[SW16(bn, kc + ac)];
                        b1 = sB[SW16(bn, kc + ac + 4)];
                    }
                    mma_tf32(acc[0][j], af0, b0, b1);
                    mma_tf32(acc[1][j], af1, b0, b1);
                }
            }
        }
    }

    // ---- epilogue ----
#pragma unroll
    for (int i = 0; i < 2; i++) {
        int r  = row0 + wm + i * 16 + arq;
        int rv0 = 1, rv1 = 1;
        if (MASK) { rv0 = rowmask[r]; rv1 = rowmask[r + 8]; }
#pragma unroll
        for (int j = 0; j < 8; j++) {
            int c = col0 + wn + j * 8 + ac * 2;
            if (c < N) {
                float v0 = alpha * acc[i][j][0];
                float v1 = alpha * acc[i][j][1];
                float v2 = alpha * acc[i][j][2];
                float v3 = alpha * acc[i][j][3];
                if (MASK) {
                    int cm0 = colmask[c], cm1 = colmask[c + 1];
                    if (rv0 == 0 || cm0 == 0) v0 = NEG_F;
                    if (rv0 == 0 || cm1 == 0) v1 = NEG_F;
                    if (rv1 == 0 || cm0 == 0) v2 = NEG_F;
                    if (rv1 == 0 || cm1 == 0) v3 = NEG_F;
                }
                *(float2*)&C[(long)r * ldc + c]       = make_float2(v0, v1);
                *(float2*)&C[(long)(r + 8) * ldc + c] = make_float2(v2, v3);
            }
        }
    }
}

// ---------------- fused projection mega-kernel ----------------
// grid (6, 544): by<16 -> q, by<32 -> vq, by<288 -> k, else vp
__global__ void __launch_bounds__(256, 2)
k_proj_all(const float* __restrict__ pep, const float* __restrict__ prot,
           const float* __restrict__ Wq,  const float* __restrict__ Wvq,
           const float* __restrict__ Wk,  const float* __restrict__ Wvp,
           float* __restrict__ q, float* __restrict__ vq,
           float* __restrict__ k, float* __restrict__ vp)
{
    int by = blockIdx.y;
    const float *A, *Bm; float* C; int row0;
    if (by < 16)        { A = pep;  Bm = Wq;  C = q;  row0 = by * BM; }
    else if (by < 32)   { A = pep;  Bm = Wvq; C = vq; row0 = (by - 32 + 16) * BM; }
    else if (by < 288)  { A = prot; Bm = Wk;  C = k;  row0 = (by - 32) * BM; }
    else                { A = prot; Bm = Wvp; C = vp; row0 = (by - 288) * BM; }
    gemm_mma<false, false, false, false>(A, Bm, C, 0, INNER, INNER,
                                         INNER, INNER, INNER, 1.0f,
                                         row0, blockIdx.x * BN, 0, 0);
}

// scores with fused masking: writes NEG_F where masked
__global__ void __launch_bounds__(256, 2)
k_scores(const float* __restrict__ q, const float* __restrict__ kb,
         float* __restrict__ attn,
         const int* __restrict__ pmask, const int* __restrict__ promask)
{
    int z = blockIdx.z;
    int b = z >> 3, h = z & 7;
    const float* A  = q  + (long)b * N_PEP * INNER + h * DH;
    const float* Bm = kb + (long)b * M_PRO * INNER + h * DH;
    float* C = attn + (long)z * N_PEP * M_PRO;
    gemm_mma<false, true, true, false>(A, Bm, C, N_PEP, M_PRO, DH,
                                       INNER, INNER, M_PRO, SCALE_F,
                                       blockIdx.y * BM, blockIdx.x * BN,
                                       pmask + b * N_PEP, promask + b * M_PRO);
}

// fused context mega-kernel: z<512 -> ctxprot split-K chunk; z>=512 -> ctxpep tile
// Both have N = DH = 96 -> TRIM=true skips the dead 25% of MMAs in wn=64 warps.
__global__ void __launch_bounds__(256, 2)
k_ctx_all(const float* __restrict__ attn, const float* __restrict__ vp,
          const float* __restrict__ vq, float* __restrict__ part,
          float* __restrict__ cq)
{
    int z = blockIdx.z;
    if (z < BATCH * HEADS * KSPLIT) {
        int bh = z >> 2, chunk = z & 3;
        int b = bh >> 3, h = bh & 7;
        const float* A  = attn + (long)bh * N_PEP * M_PRO + chunk * KCHUNK;
        const float* Bm = vp + (long)b * M_PRO * INNER + (long)chunk * KCHUNK * INNER + h * DH;
        float* C = part + (long)chunk * (BATCH * N_PEP * INNER)
                        + (long)b * N_PEP * INNER + h * DH;
        gemm_mma<false, false, false, true>(A, Bm, C, N_PEP, DH, KCHUNK,
                                            M_PRO, INNER, INNER, 1.0f, 0, 0, 0, 0);
    } else {
        int idx = z - BATCH * HEADS * KSPLIT;    // 0..2047
        int bh = idx >> 4, ry = idx & 15;
        int b = bh >> 3, h = bh & 7;
        const float* A  = attn + (long)bh * N_PEP * M_PRO;   // (K=n, M=m)
        const float* Bm = vq + (long)b * N_PEP * INNER + h * DH;
        float* C = cq + (long)b * M_PRO * INNER + h * DH;
        gemm_mma<true, false, false, true>(A, Bm, C, M_PRO, DH, N_PEP,
                                           M_PRO, INNER, INNER, 1.0f,
                                           ry * BM, 0, 0, 0);
    }
}

// reduce 4 partials -> cp
__global__ void __launch_bounds__(256)
k_reduce4(const float* __restrict__ part, float* __restrict__ cp)
{
    const long STRIDE = (long)BATCH * N_PEP * INNER;
    long i = ((long)blockIdx.x * 256 + threadIdx.x) * 4;
    if (i >= STRIDE) return;
    float4 a = *(const float4*)&part[i];
    float4 b = *(const float4*)&part[STRIDE + i];
    float4 c = *(const float4*)&part[2 * STRIDE + i];
    float4 d = *(const float4*)&part[3 * STRIDE + i];
    *(float4*)&cp[i] = make_float4(a.x + b.x + c.x + d.x, a.y + b.y + c.y + d.y,
                                   a.z + b.z + c.z + d.z, a.w + b.w + c.w + d.w);
}

// fused output projections: by<256 -> y2 (cq@Woq), else -> y1 (cp@Wop)
__global__ void __launch_bounds__(256, 2)
k_out_dual(const float* __restrict__ cq, const float* __restrict__ Woq,
           float* __restrict__ y2,
           const float* __restrict__ cp, const float* __restrict__ Wop,
           float* __restrict__ y1)
{
    if (blockIdx.y < 256) {
        gemm_mma<false, false, false, false>(cq, Woq, y2, BATCH * M_PRO, INNER, INNER,
                                             INNER, INNER, INNER, 1.0f,
                                             blockIdx.y * BM, blockIdx.x * BN, 0, 0);
    } else {
        gemm_mma<false, false, false, false>(cp, Wop, y1, BATCH * N_PEP, INNER, INNER,
                                             INNER, INNER, INNER, 1.0f,
                                             (blockIdx.y - 256) * BM, blockIdx.x * BN, 0, 0);
    }
}

// ---------------- softmax (masks pre-applied as NEG_F) ----------------
__global__ void __launch_bounds__(256)
k_softmax(float* __restrict__ attn)
{
    const int tid = threadIdx.x;
    float* p = attn + (long)blockIdx.x * M_PRO;

    float4 v0 = *(float4*)&p[tid * 4];
    float4 v1 = *(float4*)&p[1024 + tid * 4];

    float mx = fmaxf(fmaxf(fmaxf(v0.x, v0.y), fmaxf(v0.z, v0.w)),
                     fmaxf(fmaxf(v1.x, v1.y), fmaxf(v1.z, v1.w)));
#pragma unroll
    for (int o = 16; o; o >>= 1)
        mx = fmaxf(mx, __shfl_xor_sync(0xffffffff, mx, o));
    __shared__ float red[8];
    if ((tid & 31) == 0) red[tid >> 5] = mx;
    __syncthreads();
    if (tid < 8) {
        float m = red[tid];
#pragma unroll
        for (int o = 4; o; o >>= 1) m = fmaxf(m, __shfl_xor_sync(0xff, m, o));
        red[tid] = m;
    }
    __syncthreads();
    mx = red[0];

    v0.x = expf(v0.x - mx); v0.y = expf(v0.y - mx);
    v0.z = expf(v0.z - mx); v0.w = expf(v0.w - mx);
    v1.x = expf(v1.x - mx); v1.y = expf(v1.y - mx);
    v1.z = expf(v1.z - mx); v1.w = expf(v1.w - mx);
    float s = v0.x + v0.y + v0.z + v0.w + v1.x + v1.y + v1.z + v1.w;
#pragma unroll
    for (int o = 16; o; o >>= 1) s += __shfl_xor_sync(0xffffffff, s, o);
    __shared__ float red2[8];
    if ((tid & 31) == 0) red2[tid >> 5] = s;
    __syncthreads();
    if (tid < 8) {
        float t = red2[tid];
#pragma unroll
        for (int o = 4; o; o >>= 1) t += __shfl_xor_sync(0xff, t, o);
        red2[tid] = t;
    }
    __syncthreads();
    float inv = 1.0f / red2[0];

    v0.x *= inv; v0.y *= inv; v0.z *= inv; v0.w *= inv;
    v1.x *= inv; v1.y *= inv; v1.z *= inv; v1.w *= inv;
    *(float4*)&p[tid * 4] = v0;
    *(float4*)&p[1024 + tid * 4] = v1;
}

// ---------------- fused LN ----------------
__global__ void __launch_bounds__(256)
k_ln_dual(const float* __restrict__ y1, const float* __restrict__ bo1,
          const float* __restrict__ res1, float* __restrict__ out1,
          const float* __restrict__ y2, const float* __restrict__ bo2,
          const float* __restrict__ res2, float* __restrict__ out2,
          const float* __restrict__ g, const float* __restrict__ beta)
{
    const int NROW1 = BATCH * N_PEP;   // 2048
    int row = blockIdx.x;
    const float *y, *bo, *r; float* out; int lrow;
    if (row < NROW1) { y = y1; bo = bo1; r = res1; out = out1; lrow = row; }
    else             { y = y2; bo = bo2; r = res2; out = out2; lrow = row - NROW1; }
    int tid = threadIdx.x;
    const float* yp = y + (long)lrow * INNER;
    const float* rp = r + (long)lrow * INNER;

    float x[3];
    float s = 0.0f;
#pragma unroll
    for (int i = 0; i < 3; i++) {
        int c = tid + i * 256;
        x[i] = yp[c] + bo[c] + rp[c];
        s += x[i];
    }
#pragma unroll
    for (int o = 16; o; o >>= 1) s += __shfl_xor_sync(0xffffffff, s, o);
    __shared__ float red[8];
    if ((tid & 31) == 0) red[tid >> 5] = s;
    __syncthreads();
    if (tid < 8) {
        float t = red[tid];
#pragma unroll
        for (int o = 4; o; o >>= 1) t += __shfl_xor_sync(0xff, t, o);
        red[tid] = t;
    }
    __syncthreads();
    float mu = red[0] * (1.0f / INNER);

    float v = 0.0f;
#pragma unroll
    for (int i = 0; i < 3; i++) { float d = x[i] - mu; v += d * d; }
#pragma unroll
    for (int o = 16; o; o >>= 1) v += __shfl_xor_sync(0xffffffff, v, o);
    __shared__ float red2[8];
    if ((tid & 31) == 0) red2[tid >> 5] = v;
    __syncthreads();
    if (tid < 8) {
        float t = red2[tid];
#pragma unroll
        for (int o = 4; o; o >>= 1) t += __shfl_xor_sync(0xff, t, o);
        red2[tid] = t;
    }
    __syncthreads();
    float rstd = rsqrtf(red2[0] * (1.0f / INNER) + EPS_F);
#pragma unroll
    for (int i = 0; i < 3; i++) {
        int c = tid + i * 256;
        out[(long)lrow * INNER + c] = (x[i] - mu) * rstd * g[c] + beta[c];
    }
}

// ---------------- launch ----------------
extern "C" void kernel_launch(void* const* d_in, const int* in_sizes, int n_in,
                              void* d_out, int out_size)
{
    const float* peptide = (const float*)d_in[0];
    const float* protein = (const float*)d_in[1];
    const int*   pmask   = (const int*)  d_in[2];
    const int*   promask = (const int*)  d_in[3];
    const float* Wq      = (const float*)d_in[4];
    const float* Wk      = (const float*)d_in[5];
    const float* Wvp     = (const float*)d_in[6];
    const float* Wvq     = (const float*)d_in[7];
    const float* Wop     = (const float*)d_in[8];
    const float* bop     = (const float*)d_in[9];
    const float* Woq     = (const float*)d_in[10];
    const float* boq     = (const float*)d_in[11];
    const float* lng     = (const float*)d_in[12];
    const float* lnb     = (const float*)d_in[13];

    float* out = (float*)d_out;
    float* out_prot = out;                                   // (16,128,768)
    float* out_pep  = out + (long)BATCH * N_PEP * INNER;     // (16,2048,768)
    float* attn     = out_pep + (long)BATCH * M_PRO * INNER; // (16,8,128,2048)

    float *q, *k, *vp, *vq, *cp, *cq, *y1, *y2, *part;
    cudaGetSymbolAddress((void**)&q,  g_q);
    cudaGetSymbolAddress((void**)&k,  g_k);
    cudaGetSymbolAddress((void**)&vp, g_vp);
    cudaGetSymbolAddress((void**)&vq, g_vq);
    cudaGetSymbolAddress((void**)&cp, g_cp);
    cudaGetSymbolAddress((void**)&cq, g_cq);
    cudaGetSymbolAddress((void**)&y1, g_y1);
    cudaGetSymbolAddress((void**)&y2, g_y2);
    cudaGetSymbolAddress((void**)&part, g_part);

    const dim3 blk(256);

    // all four projections in one launch
    k_proj_all<<<dim3(6, 544), blk>>>(peptide, protein, Wq, Wvq, Wk, Wvp,
                                      q, vq, k, vp);

    // attention scores (mask fused) + softmax (attn lives in d_out)
    k_scores <<<dim3(16, 1, BATCH * HEADS), blk>>>(q, k, attn, pmask, promask);
    k_softmax<<<BATCH * HEADS * N_PEP, 256>>>(attn);

    // both context GEMMs in one launch (TRIM=true: N=96)
    k_ctx_all<<<dim3(1, 1, BATCH * HEADS * KSPLIT + BATCH * HEADS * 16), blk>>>(
        attn, vp, vq, part, cq);
    k_reduce4<<<(BATCH * N_PEP * INNER / 4 + 255) / 256, blk>>>(part, cp);

    // output projections (y2 + y1 fused into one launch)
    k_out_dual<<<dim3(6, 272), blk>>>(cq, Woq, y2, cp, Wop, y1);

    // bias + residual + layernorm (fused)
    k_ln_dual<<<BATCH * N_PEP + BATCH * M_PRO, 256>>>(
        y1, bop, peptide, out_prot, y2, boq, protein, out_pep, lng, lnb);
}

// round 16
// speedup vs baseline: 1.1666x; 1.0397x over previous
#include <cuda_runtime.h>
#include <math.h>

#define BATCH   16
#define N_PEP   128
#define M_PRO   2048
#define HEADS   8
#define DH      96
#define INNER   768
#define SCALE_F 0.10206207261596577f   /* 96^-0.5 */
#define NEG_F   -1000000.0f
#define EPS_F   1e-5f

#define BM 128
#define BN 128
#define BK 16
#define TILE_W 2048
#define STAGES 3
#define KSPLIT 4
#define KCHUNK (M_PRO / KSPLIT)   /* 512 */

// ---------------- scratch (device globals; no allocations) ----------------
__device__ float g_q   [BATCH * N_PEP * INNER];
__device__ float g_k   [BATCH * M_PRO * INNER];
__device__ float g_vp  [BATCH * M_PRO * INNER];
__device__ float g_vq  [BATCH * N_PEP * INNER];
__device__ float g_cp  [BATCH * N_PEP * INNER];
__device__ float g_cq  [BATCH * M_PRO * INNER];
__device__ float g_y1  [BATCH * N_PEP * INNER];
__device__ float g_y2  [BATCH * M_PRO * INNER];
__device__ float g_part[KSPLIT * BATCH * N_PEP * INNER];

// ---------------- helpers ----------------
__device__ __forceinline__ void mma_tf32(float* c, const unsigned* a,
                                         unsigned b0, unsigned b1) {
    asm volatile(
        "mma.sync.aligned.m16n8k8.row.col.f32.tf32.tf32.f32 "
        "{%0,%1,%2,%3}, {%4,%5,%6,%7}, {%8,%9}, {%0,%1,%2,%3};"
        : "+f"(c[0]), "+f"(c[1]), "+f"(c[2]), "+f"(c[3])
        : "r"(a[0]), "r"(a[1]), "r"(a[2]), "r"(a[3]), "r"(b0), "r"(b1));
}

__device__ __forceinline__ void cpasync16(unsigned* dst, const float* src, bool pred) {
    unsigned sa = (unsigned)__cvta_generic_to_shared(dst);
    int sz = pred ? 16 : 0;
    asm volatile("cp.async.cg.shared.global [%0], [%1], 16, %2;\n"
                 :: "r"(sa), "l"(src), "r"(sz));
}
#define CP_COMMIT() asm volatile("cp.async.commit_group;\n" ::)
#define CP_WAIT1()  asm volatile("cp.async.wait_group 1;\n" ::)
#define CP_WAIT0()  asm volatile("cp.async.wait_group 0;\n" ::)

// swizzled word layouts, zero padding, all accesses conflict-free:
#define SW16(r, c)  ((r) * 16  + ((c) ^ ((((r) >> 1) & 3) * 4)))
#define SW128(r, c) ((r) * 128 + ((c) ^ (((r) & 7) * 8)))

// one pipeline step with compile-time buffer indices (bulk path, nTiles % 3 == 0)
#define GEMM_TILE_STEP(TT, BUF, BUF2)                                         \
    {                                                                         \
        unsigned* sA = sAb[BUF];                                              \
        unsigned* sB = sBb[BUF];                                              \
        if ((TT) + 1 < nTiles) { CP_WAIT1(); } else { CP_WAIT0(); }           \
        __syncthreads();                                                      \
        if ((TT) + 2 < nTiles) issue((BUF2), ((TT) + 2) * BK);                \
        _Pragma("unroll")                                                     \
        for (int kc = 0; kc < BK; kc += 8) {                                  \
            unsigned af0[4], af1[4];                                          \
            if (!TA) {                                                        \
                af0[0] = sA[SW16(wm + arq,      kc + ac)];                    \
                af0[1] = sA[SW16(wm + arq + 8,  kc + ac)];                    \
                af0[2] = sA[SW16(wm + arq,      kc + ac + 4)];                \
                af0[3] = sA[SW16(wm + arq + 8,  kc + ac + 4)];                \
                af1[0] = sA[SW16(wm + arq + 16, kc + ac)];                    \
                af1[1] = sA[SW16(wm + arq + 24, kc + ac)];                    \
                af1[2] = sA[SW16(wm + arq + 16, kc + ac + 4)];                \
                af1[3] = sA[SW16(wm + arq + 24, kc + ac + 4)];                \
            } else {                                                          \
                af0[0] = sA[SW128(kc + ac,     wm + arq)];                    \
                af0[1] = sA[SW128(kc + ac,     wm + arq + 8)];                \
                af0[2] = sA[SW128(kc + ac + 4, wm + arq)];                    \
                af0[3] = sA[SW128(kc + ac + 4, wm + arq + 8)];                \
                af1[0] = sA[SW128(kc + ac,     wm + arq + 16)];               \
                af1[1] = sA[SW128(kc + ac,     wm + arq + 24)];               \
                af1[2] = sA[SW128(kc + ac + 4, wm + arq + 16)];               \
                af1[3] = sA[SW128(kc + ac + 4, wm + arq + 24)];               \
            }                                                                 \
            _Pragma("unroll")                                                 \
            for (int j = 0; j < 8; j++) {                                     \
                const int bn = wn + j * 8 + arq;                              \
                unsigned b0, b1;                                              \
                if (!TB) {                                                    \
                    b0 = sB[SW128(kc + ac,     bn)];                          \
                    b1 = sB[SW128(kc + ac + 4, bn)];                          \
                } else {                                                      \
                    b0 = sB[SW16(bn, kc + ac)];                               \
                    b1 = sB[SW16(bn, kc + ac + 4)];                           \
                }                                                             \
                mma_tf32(acc[0][j], af0, b0, b1);                             \
                mma_tf32(acc[1][j], af1, b0, b1);                             \
            }                                                                 \
        }                                                                     \
    }

// ---------------- 128x128x16 3-stage-pipelined tf32 GEMM tile ----------------
// Raw fp32 bits fed to mma.sync.tf32 (HW truncates).
// TA: A stored (K, M) row-major, lda; else (M, K).
// TB: B stored (N, K) row-major, ldb; else (K, N).
// MASK: apply attention masks in epilogue.
// TRIM: skip dead j-steps (narrow-N ctx GEMMs only).
// UNR3: tile loop unrolled by 3 with literal buffer indices (requires K/BK % 3 == 0).
template <bool TA, bool TB, bool MASK, bool TRIM, bool UNR3>
__device__ __forceinline__ void gemm_mma(const float* __restrict__ A,
                                         const float* __restrict__ Bm,
                                         float* __restrict__ C,
                                         int M, int N, int K,
                                         int lda, int ldb, int ldc,
                                         float alpha, int row0, int col0,
                                         const int* __restrict__ rowmask,
                                         const int* __restrict__ colmask)
{
    __shared__ unsigned sAb[STAGES][TILE_W];
    __shared__ unsigned sBb[STAGES][TILE_W];

    const int tid  = threadIdx.x;
    const int lane = tid & 31;
    const int wid  = tid >> 5;
    const int wm   = (wid >> 1) * 32;
    const int wn   = (wid & 1) * 64;

    int jcap = 8;
    if (TRIM) {
        jcap = (N - col0 - wn + 7) >> 3;
        if (jcap > 8) jcap = 8;
        if (jcap < 0) jcap = 0;
    }

    float acc[2][8][4];
#pragma unroll
    for (int i = 0; i < 2; i++)
#pragma unroll
        for (int j = 0; j < 8; j++)
#pragma unroll
            for (int t = 0; t < 4; t++) acc[i][j][t] = 0.0f;

    const int nTiles = K / BK;

    auto issue = [&](int buf, int k0) {
        unsigned* sA = sAb[buf];
        unsigned* sB = sBb[buf];
#pragma unroll
        for (int it = 0; it < 2; it++) {
            int idx = tid + it * 256;
            if (!TA) {
                int m  = idx >> 2;
                int kk = (idx & 3) * 4;
                cpasync16(&sA[SW16(m, kk)],
                          &A[(long)(row0 + m) * lda + k0 + kk], true);
            } else {
                int kk = idx >> 5;
                int m4 = (idx & 31) * 4;
                cpasync16(&sA[SW128(kk, m4)],
                          &A[(long)(k0 + kk) * lda + row0 + m4], true);
            }
        }
#pragma unroll
        for (int it = 0; it < 2; it++) {
            int idx = tid + it * 256;
            if (!TB) {
                int kk = idx >> 5;
                int n4 = (idx & 31) * 4;
                cpasync16(&sB[SW128(kk, n4)],
                          &Bm[(long)(k0 + kk) * ldb + col0 + n4],
                          col0 + n4 < N);
            } else {
                int n  = idx >> 2;
                int kq = (idx & 3) * 4;
                cpasync16(&sB[SW16(n, kq)],
                          &Bm[(long)(col0 + n) * ldb + k0 + kq],
                          col0 + n < N);
            }
        }
        CP_COMMIT();
    };

    const int arq = lane >> 2;
    const int ac  = lane & 3;

    issue(0, 0);
    if (nTiles > 1) issue(1, BK);

    if (UNR3) {
        // nTiles % 3 == 0 guaranteed by callers (K = 768 or 96)
#pragma unroll 1
        for (int t = 0; t < nTiles; t += 3) {
            GEMM_TILE_STEP(t,     0, 2);
            GEMM_TILE_STEP(t + 1, 1, 0);
            GEMM_TILE_STEP(t + 2, 2, 1);
        }
    } else {
        for (int t = 0; t < nTiles; t++) {
            const int buf = t % STAGES;
            unsigned* sA = sAb[buf];
            unsigned* sB = sBb[buf];

            if (t + 1 < nTiles) CP_WAIT1(); else CP_WAIT0();
            __syncthreads();
            if (t + 2 < nTiles) issue((t + 2) % STAGES, (t + 2) * BK);

#pragma unroll
            for (int kc = 0; kc < BK; kc += 8) {
                unsigned af0[4], af1[4];
                if (!TA) {
                    af0[0] = sA[SW16(wm + arq,      kc + ac)];
                    af0[1] = sA[SW16(wm + arq + 8,  kc + ac)];
                    af0[2] = sA[SW16(wm + arq,      kc + ac + 4)];
                    af0[3] = sA[SW16(wm + arq + 8,  kc + ac + 4)];
                    af1[0] = sA[SW16(wm + arq + 16, kc + ac)];
                    af1[1] = sA[SW16(wm + arq + 24, kc + ac)];
                    af1[2] = sA[SW16(wm + arq + 16, kc + ac + 4)];
                    af1[3] = sA[SW16(wm + arq + 24, kc + ac + 4)];
                } else {
                    af0[0] = sA[SW128(kc + ac,     wm + arq)];
                    af0[1] = sA[SW128(kc + ac,     wm + arq + 8)];
                    af0[2] = sA[SW128(kc + ac + 4, wm + arq)];
                    af0[3] = sA[SW128(kc + ac + 4, wm + arq + 8)];
                    af1[0] = sA[SW128(kc + ac,     wm + arq + 16)];
                    af1[1] = sA[SW128(kc + ac,     wm + arq + 24)];
                    af1[2] = sA[SW128(kc + ac + 4, wm + arq + 16)];
                    af1[3] = sA[SW128(kc + ac + 4, wm + arq + 24)];
                }
                if (!TRIM) {
#pragma unroll
                    for (int j = 0; j < 8; j++) {
                        const int bn = wn + j * 8 + arq;
                        unsigned b0, b1;
                        if (!TB) {
                            b0 = sB[SW128(kc + ac,     bn)];
                            b1 = sB[SW128(kc + ac + 4, bn)];
                        } else {
                            b0 = sB[SW16(bn, kc + ac)];
                            b1 = sB[SW16(bn, kc + ac + 4)];
                        }
                        mma_tf32(acc[0][j], af0, b0, b1);
                        mma_tf32(acc[1][j], af1, b0, b1);
                    }
                } else {
                    for (int j = 0; j < jcap; j++) {
                        const int bn = wn + j * 8 + arq;
                        unsigned b0, b1;
                        if (!TB) {
                            b0 = sB[SW128(kc + ac,     bn)];
                            b1 = sB[SW128(kc + ac + 4, bn)];
                        } else {
                            b0 = sB[SW16(bn, kc + ac)];
                            b1 = sB[SW16(bn, kc + ac + 4)];
                        }
                        mma_tf32(acc[0][j], af0, b0, b1);
                        mma_tf32(acc[1][j], af1, b0, b1);
                    }
                }
            }
        }
    }

    // ---- epilogue ----
#pragma unroll
    for (int i = 0; i < 2; i++) {
        int r  = row0 + wm + i * 16 + arq;
        int rv0 = 1, rv1 = 1;
        if (MASK) { rv0 = rowmask[r]; rv1 = rowmask[r + 8]; }
#pragma unroll
        for (int j = 0; j < 8; j++) {
            int c = col0 + wn + j * 8 + ac * 2;
            if (c < N) {
                float v0 = alpha * acc[i][j][0];
                float v1 = alpha * acc[i][j][1];
                float v2 = alpha * acc[i][j][2];
                float v3 = alpha * acc[i][j][3];
                if (MASK) {
                    int cm0 = colmask[c], cm1 = colmask[c + 1];
                    if (rv0 == 0 || cm0 == 0) v0 = NEG_F;
                    if (rv0 == 0 || cm1 == 0) v1 = NEG_F;
                    if (rv1 == 0 || cm0 == 0) v2 = NEG_F;
                    if (rv1 == 0 || cm1 == 0) v3 = NEG_F;
                }
                *(float2*)&C[(long)r * ldc + c]       = make_float2(v0, v1);
                *(float2*)&C[(long)(r + 8) * ldc + c] = make_float2(v2, v3);
            }
        }
    }
}

// ---------------- fused projection mega-kernel ----------------
// grid (6, 544): by<16 -> q, by<32 -> vq, by<288 -> k, else vp
__global__ void __launch_bounds__(256, 2)
k_proj_all(const float* __restrict__ pep, const float* __restrict__ prot,
           const float* __restrict__ Wq,  const float* __restrict__ Wvq,
           const float* __restrict__ Wk,  const float* __restrict__ Wvp,
           float* __restrict__ q, float* __restrict__ vq,
           float* __restrict__ k, float* __restrict__ vp)
{
    int by = blockIdx.y;
    const float *A, *Bm; float* C; int row0;
    if (by < 16)        { A = pep;  Bm = Wq;  C = q;  row0 = by * BM; }
    else if (by < 32)   { A = pep;  Bm = Wvq; C = vq; row0 = (by - 32 + 16) * BM; }
    else if (by < 288)  { A = prot; Bm = Wk;  C = k;  row0 = (by - 32) * BM; }
    else                { A = prot; Bm = Wvp; C = vp; row0 = (by - 288) * BM; }
    gemm_mma<false, false, false, false, true>(A, Bm, C, 0, INNER, INNER,
                                               INNER, INNER, INNER, 1.0f,
                                               row0, blockIdx.x * BN, 0, 0);
}

// scores with fused masking: writes NEG_F where masked (K = DH = 96 -> 6 tiles)
__global__ void __launch_bounds__(256, 2)
k_scores(const float* __restrict__ q, const float* __restrict__ kb,
         float* __restrict__ attn,
         const int* __restrict__ pmask, const int* __restrict__ promask)
{
    int z = blockIdx.z;
    int b = z >> 3, h = z & 7;
    const float* A  = q  + (long)b * N_PEP * INNER + h * DH;
    const float* Bm = kb + (long)b * M_PRO * INNER + h * DH;
    float* C = attn + (long)z * N_PEP * M_PRO;
    gemm_mma<false, true, true, false, true>(A, Bm, C, N_PEP, M_PRO, DH,
                                             INNER, INNER, M_PRO, SCALE_F,
                                             blockIdx.y * BM, blockIdx.x * BN,
                                             pmask + b * N_PEP, promask + b * M_PRO);
}

// fused context mega-kernel: z<512 -> ctxprot split-K chunk; z>=512 -> ctxpep tile
// Both have N = DH = 96 -> TRIM=true; nTiles 32/8 not %3 -> generic loop.
__global__ void __launch_bounds__(256, 2)
k_ctx_all(const float* __restrict__ attn, const float* __restrict__ vp,
          const float* __restrict__ vq, float* __restrict__ part,
          float* __restrict__ cq)
{
    int z = blockIdx.z;
    if (z < BATCH * HEADS * KSPLIT) {
        int bh = z >> 2, chunk = z & 3;
        int b = bh >> 3, h = bh & 7;
        const float* A  = attn + (long)bh * N_PEP * M_PRO + chunk * KCHUNK;
        const float* Bm = vp + (long)b * M_PRO * INNER + (long)chunk * KCHUNK * INNER + h * DH;
        float* C = part + (long)chunk * (BATCH * N_PEP * INNER)
                        + (long)b * N_PEP * INNER + h * DH;
        gemm_mma<false, false, false, true, false>(A, Bm, C, N_PEP, DH, KCHUNK,
                                                   M_PRO, INNER, INNER, 1.0f, 0, 0, 0, 0);
    } else {
        int idx = z - BATCH * HEADS * KSPLIT;    // 0..2047
        int bh = idx >> 4, ry = idx & 15;
        int b = bh >> 3, h = bh & 7;
        const float* A  = attn + (long)bh * N_PEP * M_PRO;   // (K=n, M=m)
        const float* Bm = vq + (long)b * N_PEP * INNER + h * DH;
        float* C = cq + (long)b * M_PRO * INNER + h * DH;
        gemm_mma<true, false, false, true, false>(A, Bm, C, M_PRO, DH, N_PEP,
                                                  M_PRO, INNER, INNER, 1.0f,
                                                  ry * BM, 0, 0, 0);
    }
}

// reduce 4 partials -> cp
__global__ void __launch_bounds__(256)
k_reduce4(const float* __restrict__ part, float* __restrict__ cp)
{
    const long STRIDE = (long)BATCH * N_PEP * INNER;
    long i = ((long)blockIdx.x * 256 + threadIdx.x) * 4;
    if (i >= STRIDE) return;
    float4 a = *(const float4*)&part[i];
    float4 b = *(const float4*)&part[STRIDE + i];
    float4 c = *(const float4*)&part[2 * STRIDE + i];
    float4 d = *(const float4*)&part[3 * STRIDE + i];
    *(float4*)&cp[i] = make_float4(a.x + b.x + c.x + d.x, a.y + b.y + c.y + d.y,
                                   a.z + b.z + c.z + d.z, a.w + b.w + c.w + d.w);
}

// fused output projections: by<256 -> y2 (cq@Woq), else -> y1 (cp@Wop)
__global__ void __launch_bounds__(256, 2)
k_out_dual(const float* __restrict__ cq, const float* __restrict__ Woq,
           float* __restrict__ y2,
           const float* __restrict__ cp, const float* __restrict__ Wop,
           float* __restrict__ y1)
{
    if (blockIdx.y < 256) {
        gemm_mma<false, false, false, false, true>(cq, Woq, y2, BATCH * M_PRO, INNER, INNER,
                                                   INNER, INNER, INNER, 1.0f,
                                                   blockIdx.y * BM, blockIdx.x * BN, 0, 0);
    } else {
        gemm_mma<false, false, false, false, true>(cp, Wop, y1, BATCH * N_PEP, INNER, INNER,
                                                   INNER, INNER, INNER, 1.0f,
                                                   (blockIdx.y - 256) * BM, blockIdx.x * BN, 0, 0);
    }
}

// ---------------- softmax (masks pre-applied as NEG_F) ----------------
__global__ void __launch_bounds__(256)
k_softmax(float* __restrict__ attn)
{
    const int tid = threadIdx.x;
    float* p = attn + (long)blockIdx.x * M_PRO;

    float4 v0 = *(float4*)&p[tid * 4];
    float4 v1 = *(float4*)&p[1024 + tid * 4];

    float mx = fmaxf(fmaxf(fmaxf(v0.x, v0.y), fmaxf(v0.z, v0.w)),
                     fmaxf(fmaxf(v1.x, v1.y), fmaxf(v1.z, v1.w)));
#pragma unroll
    for (int o = 16; o; o >>= 1)
        mx = fmaxf(mx, __shfl_xor_sync(0xffffffff, mx, o));
    __shared__ float red[8];
    if ((tid & 31) == 0) red[tid >> 5] = mx;
    __syncthreads();
    if (tid < 8) {
        float m = red[tid];
#pragma unroll
        for (int o = 4; o; o >>= 1) m = fmaxf(m, __shfl_xor_sync(0xff, m, o));
        red[tid] = m;
    }
    __syncthreads();
    mx = red[0];

    v0.x = expf(v0.x - mx); v0.y = expf(v0.y - mx);
    v0.z = expf(v0.z - mx); v0.w = expf(v0.w - mx);
    v1.x = expf(v1.x - mx); v1.y = expf(v1.y - mx);
    v1.z = expf(v1.z - mx); v1.w = expf(v1.w - mx);
    float s = v0.x + v0.y + v0.z + v0.w + v1.x + v1.y + v1.z + v1.w;
#pragma unroll
    for (int o = 16; o; o >>= 1) s += __shfl_xor_sync(0xffffffff, s, o);
    __shared__ float red2[8];
    if ((tid & 31) == 0) red2[tid >> 5] = s;
    __syncthreads();
    if (tid < 8) {
        float t = red2[tid];
#pragma unroll
        for (int o = 4; o; o >>= 1) t += __shfl_xor_sync(0xff, t, o);
        red2[tid] = t;
    }
    __syncthreads();
    float inv = 1.0f / red2[0];

    v0.x *= inv; v0.y *= inv; v0.z *= inv; v0.w *= inv;
    v1.x *= inv; v1.y *= inv; v1.z *= inv; v1.w *= inv;
    *(float4*)&p[tid * 4] = v0;
    *(float4*)&p[1024 + tid * 4] = v1;
}

// ---------------- fused LN ----------------
__global__ void __launch_bounds__(256)
k_ln_dual(const float* __restrict__ y1, const float* __restrict__ bo1,
          const float* __restrict__ res1, float* __restrict__ out1,
          const float* __restrict__ y2, const float* __restrict__ bo2,
          const float* __restrict__ res2, float* __restrict__ out2,
          const float* __restrict__ g, const float* __restrict__ beta)
{
    const int NROW1 = BATCH * N_PEP;   // 2048
    int row = blockIdx.x;
    const float *y, *bo, *r; float* out; int lrow;
    if (row < NROW1) { y = y1; bo = bo1; r = res1; out = out1; lrow = row; }
    else             { y = y2; bo = bo2; r = res2; out = out2; lrow = row - NROW1; }
    int tid = threadIdx.x;
    const float* yp = y + (long)lrow * INNER;
    const float* rp = r + (long)lrow * INNER;

    float x[3];
    float s = 0.0f;
#pragma unroll
    for (int i = 0; i < 3; i++) {
        int c = tid + i * 256;
        x[i] = yp[c] + bo[c] + rp[c];
        s += x[i];
    }
#pragma unroll
    for (int o = 16; o; o >>= 1) s += __shfl_xor_sync(0xffffffff, s, o);
    __shared__ float red[8];
    if ((tid & 31) == 0) red[tid >> 5] = s;
    __syncthreads();
    if (tid < 8) {
        float t = red[tid];
#pragma unroll
        for (int o = 4; o; o >>= 1) t += __shfl_xor_sync(0xff, t, o);
        red[tid] = t;
    }
    __syncthreads();
    float mu = red[0] * (1.0f / INNER);

    float v = 0.0f;
#pragma unroll
    for (int i = 0; i < 3; i++) { float d = x[i] - mu; v += d * d; }
#pragma unroll
    for (int o = 16; o; o >>= 1) v += __shfl_xor_sync(0xffffffff, v, o);
    __shared__ float red2[8];
    if ((tid & 31) == 0) red2[tid >> 5] = v;
    __syncthreads();
    if (tid < 8) {
        float t = red2[tid];
#pragma unroll
        for (int o = 4; o; o >>= 1) t += __shfl_xor_sync(0xff, t, o);
        red2[tid] = t;
    }
    __syncthreads();
    float rstd = rsqrtf(red2[0] * (1.0f / INNER) + EPS_F);
#pragma unroll
    for (int i = 0; i < 3; i++) {
        int c = tid + i * 256;
        out[(long)lrow * INNER + c] = (x[i] - mu) * rstd * g[c] + beta[c];
    }
}

// ---------------- launch ----------------
extern "C" void kernel_launch(void* const* d_in, const int* in_sizes, int n_in,
                              void* d_out, int out_size)
{
    const float* peptide = (const float*)d_in[0];
    const float* protein = (const float*)d_in[1];
    const int*   pmask   = (const int*)  d_in[2];
    const int*   promask = (const int*)  d_in[3];
    const float* Wq      = (const float*)d_in[4];
    const float* Wk      = (const float*)d_in[5];
    const float* Wvp     = (const float*)d_in[6];
    const float* Wvq     = (const float*)d_in[7];
    const float* Wop     = (const float*)d_in[8];
    const float* bop     = (const float*)d_in[9];
    const float* Woq     = (const float*)d_in[10];
    const float* boq     = (const float*)d_in[11];
    const float* lng     = (const float*)d_in[12];
    const float* lnb     = (const float*)d_in[13];

    float* out = (float*)d_out;
    float* out_prot = out;                                   // (16,128,768)
    float* out_pep  = out + (long)BATCH * N_PEP * INNER;     // (16,2048,768)
    float* attn     = out_pep + (long)BATCH * M_PRO * INNER; // (16,8,128,2048)

    float *q, *k, *vp, *vq, *cp, *cq, *y1, *y2, *part;
    cudaGetSymbolAddress((void**)&q,  g_q);
    cudaGetSymbolAddress((void**)&k,  g_k);
    cudaGetSymbolAddress((void**)&vp, g_vp);
    cudaGetSymbolAddress((void**)&vq, g_vq);
    cudaGetSymbolAddress((void**)&cp, g_cp);
    cudaGetSymbolAddress((void**)&cq, g_cq);
    cudaGetSymbolAddress((void**)&y1, g_y1);
    cudaGetSymbolAddress((void**)&y2, g_y2);
    cudaGetSymbolAddress((void**)&part, g_part);

    const dim3 blk(256);

    // all four projections in one launch
    k_proj_all<<<dim3(6, 544), blk>>>(peptide, protein, Wq, Wvq, Wk, Wvp,
                                      q, vq, k, vp);

    // attention scores (mask fused) + softmax (attn lives in d_out)
    k_scores <<<dim3(16, 1, BATCH * HEADS), blk>>>(q, k, attn, pmask, promask);
    k_softmax<<<BATCH * HEADS * N_PEP, 256>>>(attn);

    // both context GEMMs in one launch (TRIM=true: N=96)
    k_ctx_all<<<dim3(1, 1, BATCH * HEADS * KSPLIT + BATCH * HEADS * 16), blk>>>(
        attn, vp, vq, part, cq);
    k_reduce4<<<(BATCH * N_PEP * INNER / 4 + 255) / 256, blk>>>(part, cp);

    // output projections (y2 + y1 fused into one launch)
    k_out_dual<<<dim3(6, 272), blk>>>(cq, Woq, y2, cp, Wop, y1);

    // bias + residual + layernorm (fused)
    k_ln_dual<<<BATCH * N_PEP + BATCH * M_PRO, 256>>>(
        y1, bop, peptide, out_prot, y2, boq, protein, out_pep, lng, lnb);
}

// round 17
// speedup vs baseline: 1.1798x; 1.0114x over previous
#include <cuda_runtime.h>
#include <math.h>

#define BATCH   16
#define N_PEP   128
#define M_PRO   2048
#define HEADS   8
#define DH      96
#define INNER   768
#define SCALE_F 0.10206207261596577f   /* 96^-0.5 */
#define NEG_F   -1000000.0f
#define EPS_F   1e-5f

#define BM 128
#define BN 128
#define BK 16
#define TILE_W 2048
#define STAGES 3
#define KSPLIT 4
#define KCHUNK (M_PRO / KSPLIT)   /* 512 */

// ---------------- scratch (device globals; no allocations) ----------------
__device__ float g_q   [BATCH * N_PEP * INNER];
__device__ float g_k   [BATCH * M_PRO * INNER];
__device__ float g_vp  [BATCH * M_PRO * INNER];
__device__ float g_vq  [BATCH * N_PEP * INNER];
__device__ float g_cp  [BATCH * N_PEP * INNER];
__device__ float g_cq  [BATCH * M_PRO * INNER];
__device__ float g_y1  [BATCH * N_PEP * INNER];
__device__ float g_y2  [BATCH * M_PRO * INNER];
__device__ float g_part[KSPLIT * BATCH * N_PEP * INNER];

// ---------------- helpers ----------------
__device__ __forceinline__ void mma_tf32(float* c, const unsigned* a,
                                         unsigned b0, unsigned b1) {
    asm volatile(
        "mma.sync.aligned.m16n8k8.row.col.f32.tf32.tf32.f32 "
        "{%0,%1,%2,%3}, {%4,%5,%6,%7}, {%8,%9}, {%0,%1,%2,%3};"
        : "+f"(c[0]), "+f"(c[1]), "+f"(c[2]), "+f"(c[3])
        : "r"(a[0]), "r"(a[1]), "r"(a[2]), "r"(a[3]), "r"(b0), "r"(b1));
}

__device__ __forceinline__ void cpasync16(unsigned* dst, const float* src, bool pred) {
    unsigned sa = (unsigned)__cvta_generic_to_shared(dst);
    int sz = pred ? 16 : 0;
    asm volatile("cp.async.cg.shared.global [%0], [%1], 16, %2;\n"
                 :: "r"(sa), "l"(src), "r"(sz));
}
#define CP_COMMIT() asm volatile("cp.async.commit_group;\n" ::)
#define CP_WAIT1()  asm volatile("cp.async.wait_group 1;\n" ::)
#define CP_WAIT0()  asm volatile("cp.async.wait_group 0;\n" ::)

// swizzled word layouts, zero padding, all accesses conflict-free:
#define SW16(r, c)  ((r) * 16  + ((c) ^ ((((r) >> 1) & 3) * 4)))
#define SW128(r, c) ((r) * 128 + ((c) ^ (((r) & 7) * 8)))

// one pipeline step with compile-time buffer indices
#define GEMM_TILE_STEP(TT, BUF, BUF2)                                         \
    {                                                                         \
        unsigned* sA = sAb[BUF];                                              \
        unsigned* sB = sBb[BUF];                                              \
        if ((TT) + 1 < nTiles) { CP_WAIT1(); } else { CP_WAIT0(); }           \
        __syncthreads();                                                      \
        if ((TT) + 2 < nTiles) issue((BUF2), ((TT) + 2) * BK);                \
        _Pragma("unroll")                                                     \
        for (int kc = 0; kc < BK; kc += 8) {                                  \
            unsigned af0[4], af1[4];                                          \
            if (!TA) {                                                        \
                af0[0] = sA[SW16(wm + arq,      kc + ac)];                    \
                af0[1] = sA[SW16(wm + arq + 8,  kc + ac)];                    \
                af0[2] = sA[SW16(wm + arq,      kc + ac + 4)];                \
                af0[3] = sA[SW16(wm + arq + 8,  kc + ac + 4)];                \
                af1[0] = sA[SW16(wm + arq + 16, kc + ac)];                    \
                af1[1] = sA[SW16(wm + arq + 24, kc + ac)];                    \
                af1[2] = sA[SW16(wm + arq + 16, kc + ac + 4)];                \
                af1[3] = sA[SW16(wm + arq + 24, kc + ac + 4)];                \
            } else {                                                          \
                af0[0] = sA[SW128(kc + ac,     wm + arq)];                    \
                af0[1] = sA[SW128(kc + ac,     wm + arq + 8)];                \
                af0[2] = sA[SW128(kc + ac + 4, wm + arq)];                    \
                af0[3] = sA[SW128(kc + ac + 4, wm + arq + 8)];                \
                af1[0] = sA[SW128(kc + ac,     wm + arq + 16)];               \
                af1[1] = sA[SW128(kc + ac,     wm + arq + 24)];               \
                af1[2] = sA[SW128(kc + ac + 4, wm + arq + 16)];               \
                af1[3] = sA[SW128(kc + ac + 4, wm + arq + 24)];               \
            }                                                                 \
            if (!TRIM) {                                                      \
                _Pragma("unroll")                                             \
                for (int j = 0; j < 8; j++) {                                 \
                    const int bn = wn + j * 8 + arq;                          \
                    unsigned b0, b1;                                          \
                    if (!TB) {                                                \
                        b0 = sB[SW128(kc + ac,     bn)];                      \
                        b1 = sB[SW128(kc + ac + 4, bn)];                      \
                    } else {                                                  \
                        b0 = sB[SW16(bn, kc + ac)];                           \
                        b1 = sB[SW16(bn, kc + ac + 4)];                       \
                    }                                                         \
                    mma_tf32(acc[0][j], af0, b0, b1);                         \
                    mma_tf32(acc[1][j], af1, b0, b1);                         \
                }                                                             \
            } else {                                                          \
                for (int j = 0; j < jcap; j++) {                              \
                    const int bn = wn + j * 8 + arq;                          \
                    unsigned b0, b1;                                          \
                    if (!TB) {                                                \
                        b0 = sB[SW128(kc + ac,     bn)];                      \
                        b1 = sB[SW128(kc + ac + 4, bn)];                      \
                    } else {                                                  \
                        b0 = sB[SW16(bn, kc + ac)];                           \
                        b1 = sB[SW16(bn, kc + ac + 4)];                       \
                    }                                                         \
                    mma_tf32(acc[0][j], af0, b0, b1);                         \
                    mma_tf32(acc[1][j], af1, b0, b1);                         \
                }                                                             \
            }                                                                 \
        }                                                                     \
    }

// ---------------- 128x128x16 3-stage-pipelined tf32 GEMM tile ----------------
// Raw fp32 bits fed to mma.sync.tf32 (HW truncates).
// TA: A stored (K, M) row-major, lda; else (M, K).
// TB: B stored (N, K) row-major, ldb; else (K, N).
// MASK: apply attention masks in epilogue.
// TRIM: skip dead j-steps (narrow-N ctx GEMMs only).
// UNR3:   K/BK % 3 == 0 -> 3-step unrolled loop, literal buffers.
// UNR3R2: K/BK % 3 == 2 -> 3-step unrolled loop + 2-step epilogue, literal buffers.
template <bool TA, bool TB, bool MASK, bool TRIM, bool UNR3, bool UNR3R2>
__device__ __forceinline__ void gemm_mma(const float* __restrict__ A,
                                         const float* __restrict__ Bm,
                                         float* __restrict__ C,
                                         int M, int N, int K,
                                         int lda, int ldb, int ldc,
                                         float alpha, int row0, int col0,
                                         const int* __restrict__ rowmask,
                                         const int* __restrict__ colmask)
{
    __shared__ unsigned sAb[STAGES][TILE_W];
    __shared__ unsigned sBb[STAGES][TILE_W];

    const int tid  = threadIdx.x;
    const int lane = tid & 31;
    const int wid  = tid >> 5;
    const int wm   = (wid >> 1) * 32;
    const int wn   = (wid & 1) * 64;

    int jcap = 8;
    if (TRIM) {
        jcap = (N - col0 - wn + 7) >> 3;
        if (jcap > 8) jcap = 8;
        if (jcap < 0) jcap = 0;
    }

    float acc[2][8][4];
#pragma unroll
    for (int i = 0; i < 2; i++)
#pragma unroll
        for (int j = 0; j < 8; j++)
#pragma unroll
            for (int t = 0; t < 4; t++) acc[i][j][t] = 0.0f;

    const int nTiles = K / BK;

    auto issue = [&](int buf, int k0) {
        unsigned* sA = sAb[buf];
        unsigned* sB = sBb[buf];
#pragma unroll
        for (int it = 0; it < 2; it++) {
            int idx = tid + it * 256;
            if (!TA) {
                int m  = idx >> 2;
                int kk = (idx & 3) * 4;
                cpasync16(&sA[SW16(m, kk)],
                          &A[(long)(row0 + m) * lda + k0 + kk], true);
            } else {
                int kk = idx >> 5;
                int m4 = (idx & 31) * 4;
                cpasync16(&sA[SW128(kk, m4)],
                          &A[(long)(k0 + kk) * lda + row0 + m4], true);
            }
        }
#pragma unroll
        for (int it = 0; it < 2; it++) {
            int idx = tid + it * 256;
            if (!TB) {
                int kk = idx >> 5;
                int n4 = (idx & 31) * 4;
                cpasync16(&sB[SW128(kk, n4)],
                          &Bm[(long)(k0 + kk) * ldb + col0 + n4],
                          col0 + n4 < N);
            } else {
                int n  = idx >> 2;
                int kq = (idx & 3) * 4;
                cpasync16(&sB[SW16(n, kq)],
                          &Bm[(long)(col0 + n) * ldb + k0 + kq],
                          col0 + n < N);
            }
        }
        CP_COMMIT();
    };

    const int arq = lane >> 2;
    const int ac  = lane & 3;

    issue(0, 0);
    if (nTiles > 1) issue(1, BK);

    if (UNR3) {
        // nTiles % 3 == 0 (K = 768)
#pragma unroll 1
        for (int t = 0; t < nTiles; t += 3) {
            GEMM_TILE_STEP(t,     0, 2);
            GEMM_TILE_STEP(t + 1, 1, 0);
            GEMM_TILE_STEP(t + 2, 2, 1);
        }
    } else if (UNR3R2) {
        // nTiles % 3 == 2 (K = 512 -> 32 tiles, K = 128 -> 8 tiles)
        int t = 0;
#pragma unroll 1
        for (; t + 3 <= nTiles - 2; t += 3) {
            GEMM_TILE_STEP(t,     0, 2);
            GEMM_TILE_STEP(t + 1, 1, 0);
            GEMM_TILE_STEP(t + 2, 2, 1);
        }
        // t == nTiles-2 here; (nTiles-2) % 3 == 0 -> buffers 0 then 1
        GEMM_TILE_STEP(t,     0, 2);
        GEMM_TILE_STEP(t + 1, 1, 0);
    } else {
        for (int t = 0; t < nTiles; t++) {
            const int buf = t % STAGES;
            {
                unsigned* sA = sAb[buf];
                unsigned* sB = sBb[buf];

                if (t + 1 < nTiles) CP_WAIT1(); else CP_WAIT0();
                __syncthreads();
                if (t + 2 < nTiles) issue((t + 2) % STAGES, (t + 2) * BK);

#pragma unroll
                for (int kc = 0; kc < BK; kc += 8) {
                    unsigned af0[4], af1[4];
                    if (!TA) {
                        af0[0] = sA[SW16(wm + arq,      kc + ac)];
                        af0[1] = sA[SW16(wm + arq + 8,  kc + ac)];
                        af0[2] = sA[SW16(wm + arq,      kc + ac + 4)];
                        af0[3] = sA[SW16(wm + arq + 8,  kc + ac + 4)];
                        af1[0] = sA[SW16(wm + arq + 16, kc + ac)];
                        af1[1] = sA[SW16(wm + arq + 24, kc + ac)];
                        af1[2] = sA[SW16(wm + arq + 16, kc + ac + 4)];
                        af1[3] = sA[SW16(wm + arq + 24, kc + ac + 4)];
                    } else {
                        af0[0] = sA[SW128(kc + ac,     wm + arq)];
                        af0[1] = sA[SW128(kc + ac,     wm + arq + 8)];
                        af0[2] = sA[SW128(kc + ac + 4, wm + arq)];
                        af0[3] = sA[SW128(kc + ac + 4, wm + arq + 8)];
                        af1[0] = sA[SW128(kc + ac,     wm + arq + 16)];
                        af1[1] = sA[SW128(kc + ac,     wm + arq + 24)];
                        af1[2] = sA[SW128(kc + ac + 4, wm + arq + 16)];
                        af1[3] = sA[SW128(kc + ac + 4, wm + arq + 24)];
                    }
                    if (!TRIM) {
#pragma unroll
                        for (int j = 0; j < 8; j++) {
                            const int bn = wn + j * 8 + arq;
                            unsigned b0, b1;
                            if (!TB) {
                                b0 = sB[SW128(kc + ac,     bn)];
                                b1 = sB[SW128(kc + ac + 4, bn)];
                            } else {
                                b0 = sB[SW16(bn, kc + ac)];
                                b1 = sB[SW16(bn, kc + ac + 4)];
                            }
                            mma_tf32(acc[0][j], af0, b0, b1);
                            mma_tf32(acc[1][j], af1, b0, b1);
                        }
                    } else {
                        for (int j = 0; j < jcap; j++) {
                            const int bn = wn + j * 8 + arq;
                            unsigned b0, b1;
                            if (!TB) {
                                b0 = sB[SW128(kc + ac,     bn)];
                                b1 = sB[SW128(kc + ac + 4, bn)];
                            } else {
                                b0 = sB[SW16(bn, kc + ac)];
                                b1 = sB[SW16(bn, kc + ac + 4)];
                            }
                            mma_tf32(acc[0][j], af0, b0, b1);
                            mma_tf32(acc[1][j], af1, b0, b1);
                        }
                    }
                }
            }
        }
    }

    // ---- epilogue ----
#pragma unroll
    for (int i = 0; i < 2; i++) {
        int r  = row0 + wm + i * 16 + arq;
        int rv0 = 1, rv1 = 1;
        if (MASK) { rv0 = rowmask[r]; rv1 = rowmask[r + 8]; }
#pragma unroll
        for (int j = 0; j < 8; j++) {
            int c = col0 + wn + j * 8 + ac * 2;
            if (c < N) {
                float v0 = alpha * acc[i][j][0];
                float v1 = alpha * acc[i][j][1];
                float v2 = alpha * acc[i][j][2];
                float v3 = alpha * acc[i][j][3];
                if (MASK) {
                    int cm0 = colmask[c], cm1 = colmask[c + 1];
                    if (rv0 == 0 || cm0 == 0) v0 = NEG_F;
                    if (rv0 == 0 || cm1 == 0) v1 = NEG_F;
                    if (rv1 == 0 || cm0 == 0) v2 = NEG_F;
                    if (rv1 == 0 || cm1 == 0) v3 = NEG_F;
                }
                *(float2*)&C[(long)r * ldc + c]       = make_float2(v0, v1);
                *(float2*)&C[(long)(r + 8) * ldc + c] = make_float2(v2, v3);
            }
        }
    }
}

// ---------------- fused projection mega-kernel ----------------
// grid (6, 544): by<16 -> q, by<32 -> vq, by<288 -> k, else vp
__global__ void __launch_bounds__(256, 2)
k_proj_all(const float* __restrict__ pep, const float* __restrict__ prot,
           const float* __restrict__ Wq,  const float* __restrict__ Wvq,
           const float* __restrict__ Wk,  const float* __restrict__ Wvp,
           float* __restrict__ q, float* __restrict__ vq,
           float* __restrict__ k, float* __restrict__ vp)
{
    int by = blockIdx.y;
    const float *A, *Bm; float* C; int row0;
    if (by < 16)        { A = pep;  Bm = Wq;  C = q;  row0 = by * BM; }
    else if (by < 32)   { A = pep;  Bm = Wvq; C = vq; row0 = (by - 32 + 16) * BM; }
    else if (by < 288)  { A = prot; Bm = Wk;  C = k;  row0 = (by - 32) * BM; }
    else                { A = prot; Bm = Wvp; C = vp; row0 = (by - 288) * BM; }
    gemm_mma<false, false, false, false, true, false>(A, Bm, C, 0, INNER, INNER,
                                                      INNER, INNER, INNER, 1.0f,
                                                      row0, blockIdx.x * BN, 0, 0);
}

// scores with fused masking: writes NEG_F where masked (K = DH = 96 -> 6 tiles)
__global__ void __launch_bounds__(256, 2)
k_scores(const float* __restrict__ q, const float* __restrict__ kb,
         float* __restrict__ attn,
         const int* __restrict__ pmask, const int* __restrict__ promask)
{
    int z = blockIdx.z;
    int b = z >> 3, h = z & 7;
    const float* A  = q  + (long)b * N_PEP * INNER + h * DH;
    const float* Bm = kb + (long)b * M_PRO * INNER + h * DH;
    float* C = attn + (long)z * N_PEP * M_PRO;
    gemm_mma<false, true, true, false, true, false>(A, Bm, C, N_PEP, M_PRO, DH,
                                                    INNER, INNER, M_PRO, SCALE_F,
                                                    blockIdx.y * BM, blockIdx.x * BN,
                                                    pmask + b * N_PEP, promask + b * M_PRO);
}

// fused context mega-kernel: z<512 -> ctxprot split-K chunk; z>=512 -> ctxpep tile
// Both N = DH = 96 -> TRIM; nTiles 32/8 (%3 == 2) -> UNR3R2 literal buffers.
__global__ void __launch_bounds__(256, 2)
k_ctx_all(const float* __restrict__ attn, const float* __restrict__ vp,
          const float* __restrict__ vq, float* __restrict__ part,
          float* __restrict__ cq)
{
    int z = blockIdx.z;
    if (z < BATCH * HEADS * KSPLIT) {
        int bh = z >> 2, chunk = z & 3;
        int b = bh >> 3, h = bh & 7;
        const float* A  = attn + (long)bh * N_PEP * M_PRO + chunk * KCHUNK;
        const float* Bm = vp + (long)b * M_PRO * INNER + (long)chunk * KCHUNK * INNER + h * DH;
        float* C = part + (long)chunk * (BATCH * N_PEP * INNER)
                        + (long)b * N_PEP * INNER + h * DH;
        gemm_mma<false, false, false, true, false, true>(A, Bm, C, N_PEP, DH, KCHUNK,
                                                         M_PRO, INNER, INNER, 1.0f,
                                                         0, 0, 0, 0);
    } else {
        int idx = z - BATCH * HEADS * KSPLIT;    // 0..2047
        int bh = idx >> 4, ry = idx & 15;
        int b = bh >> 3, h = bh & 7;
        const float* A  = attn + (long)bh * N_PEP * M_PRO;   // (K=n, M=m)
        const float* Bm = vq + (long)b * N_PEP * INNER + h * DH;
        float* C = cq + (long)b * M_PRO * INNER + h * DH;
        gemm_mma<true, false, false, true, false, true>(A, Bm, C, M_PRO, DH, N_PEP,
                                                        M_PRO, INNER, INNER, 1.0f,
                                                        ry * BM, 0, 0, 0);
    }
}

// reduce 4 partials -> cp
__global__ void __launch_bounds__(256)
k_reduce4(const float* __restrict__ part, float* __restrict__ cp)
{
    const long STRIDE = (long)BATCH * N_PEP * INNER;
    long i = ((long)blockIdx.x * 256 + threadIdx.x) * 4;
    if (i >= STRIDE) return;
    float4 a = *(const float4*)&part[i];
    float4 b = *(const float4*)&part[STRIDE + i];
    float4 c = *(const float4*)&part[2 * STRIDE + i];
    float4 d = *(const float4*)&part[3 * STRIDE + i];
    *(float4*)&cp[i] = make_float4(a.x + b.x + c.x + d.x, a.y + b.y + c.y + d.y,
                                   a.z + b.z + c.z + d.z, a.w + b.w + c.w + d.w);
}

// fused output projections: by<256 -> y2 (cq@Woq), else -> y1 (cp@Wop)
__global__ void __launch_bounds__(256, 2)
k_out_dual(const float* __restrict__ cq, const float* __restrict__ Woq,
           float* __restrict__ y2,
           const float* __restrict__ cp, const float* __restrict__ Wop,
           float* __restrict__ y1)
{
    if (blockIdx.y < 256) {
        gemm_mma<false, false, false, false, true, false>(cq, Woq, y2, BATCH * M_PRO, INNER, INNER,
                                                          INNER, INNER, INNER, 1.0f,
                                                          blockIdx.y * BM, blockIdx.x * BN, 0, 0);
    } else {
        gemm_mma<false, false, false, false, true, false>(cp, Wop, y1, BATCH * N_PEP, INNER, INNER,
                                                          INNER, INNER, INNER, 1.0f,
                                                          (blockIdx.y - 256) * BM, blockIdx.x * BN, 0, 0);
    }
}

// ---------------- softmax (masks pre-applied as NEG_F) ----------------
__global__ void __launch_bounds__(256)
k_softmax(float* __restrict__ attn)
{
    const int tid = threadIdx.x;
    float* p = attn + (long)blockIdx.x * M_PRO;

    float4 v0 = *(float4*)&p[tid * 4];
    float4 v1 = *(float4*)&p[1024 + tid * 4];

    float mx = fmaxf(fmaxf(fmaxf(v0.x, v0.y), fmaxf(v0.z, v0.w)),
                     fmaxf(fmaxf(v1.x, v1.y), fmaxf(v1.z, v1.w)));
#pragma unroll
    for (int o = 16; o; o >>= 1)
        mx = fmaxf(mx, __shfl_xor_sync(0xffffffff, mx, o));
    __shared__ float red[8];
    if ((tid & 31) == 0) red[tid >> 5] = mx;
    __syncthreads();
    if (tid < 8) {
        float m = red[tid];
#pragma unroll
        for (int o = 4; o; o >>= 1) m = fmaxf(m, __shfl_xor_sync(0xff, m, o));
        red[tid] = m;
    }
    __syncthreads();
    mx = red[0];

    v0.x = expf(v0.x - mx); v0.y = expf(v0.y - mx);
    v0.z = expf(v0.z - mx); v0.w = expf(v0.w - mx);
    v1.x = expf(v1.x - mx); v1.y = expf(v1.y - mx);
    v1.z = expf(v1.z - mx); v1.w = expf(v1.w - mx);
    float s = v0.x + v0.y + v0.z + v0.w + v1.x + v1.y + v1.z + v1.w;
#pragma unroll
    for (int o = 16; o; o >>= 1) s += __shfl_xor_sync(0xffffffff, s, o);
    __shared__ float red2[8];
    if ((tid & 31) == 0) red2[tid >> 5] = s;
    __syncthreads();
    if (tid < 8) {
        float t = red2[tid];
#pragma unroll
        for (int o = 4; o; o >>= 1) t += __shfl_xor_sync(0xff, t, o);
        red2[tid] = t;
    }
    __syncthreads();
    float inv = 1.0f / red2[0];

    v0.x *= inv; v0.y *= inv; v0.z *= inv; v0.w *= inv;
    v1.x *= inv; v1.y *= inv; v1.z *= inv; v1.w *= inv;
    *(float4*)&p[tid * 4] = v0;
    *(float4*)&p[1024 + tid * 4] = v1;
}

// ---------------- fused LN ----------------
__global__ void __launch_bounds__(256)
k_ln_dual(const float* __restrict__ y1, const float* __restrict__ bo1,
          const float* __restrict__ res1, float* __restrict__ out1,
          const float* __restrict__ y2, const float* __restrict__ bo2,
          const float* __restrict__ res2, float* __restrict__ out2,
          const float* __restrict__ g, const float* __restrict__ beta)
{
    const int NROW1 = BATCH * N_PEP;   // 2048
    int row = blockIdx.x;
    const float *y, *bo, *r; float* out; int lrow;
    if (row < NROW1) { y = y1; bo = bo1; r = res1; out = out1; lrow = row; }
    else             { y = y2; bo = bo2; r = res2; out = out2; lrow = row - NROW1; }
    int tid = threadIdx.x;
    const float* yp = y + (long)lrow * INNER;
    const float* rp = r + (long)lrow * INNER;

    float x[3];
    float s = 0.0f;
#pragma unroll
    for (int i = 0; i < 3; i++) {
        int c = tid + i * 256;
        x[i] = yp[c] + bo[c] + rp[c];
        s += x[i];
    }
#pragma unroll
    for (int o = 16; o; o >>= 1) s += __shfl_xor_sync(0xffffffff, s, o);
    __shared__ float red[8];
    if ((tid & 31) == 0) red[tid >> 5] = s;
    __syncthreads();
    if (tid < 8) {
        float t = red[tid];
#pragma unroll
        for (int o = 4; o; o >>= 1) t += __shfl_xor_sync(0xff, t, o);
        red[tid] = t;
    }
    __syncthreads();
    float mu = red[0] * (1.0f / INNER);

    float v = 0.0f;
#pragma unroll
    for (int i = 0; i < 3; i++) { float d = x[i] - mu; v += d * d; }
#pragma unroll
    for (int o = 16; o; o >>= 1) v += __shfl_xor_sync(0xffffffff, v, o);
    __shared__ float red2[8];
    if ((tid & 31) == 0) red2[tid >> 5] = v;
    __syncthreads();
    if (tid < 8) {
        float t = red2[tid];
#pragma unroll
        for (int o = 4; o; o >>= 1) t += __shfl_xor_sync(0xff, t, o);
        red2[tid] = t;
    }
    __syncthreads();
    float rstd = rsqrtf(red2[0] * (1.0f / INNER) + EPS_F);
#pragma unroll
    for (int i = 0; i < 3; i++) {
        int c = tid + i * 256;
        out[(long)lrow * INNER + c] = (x[i] - mu) * rstd * g[c] + beta[c];
    }
}

// ---------------- launch ----------------
extern "C" void kernel_launch(void* const* d_in, const int* in_sizes, int n_in,
                              void* d_out, int out_size)
{
    const float* peptide = (const float*)d_in[0];
    const float* protein = (const float*)d_in[1];
    const int*   pmask   = (const int*)  d_in[2];
    const int*   promask = (const int*)  d_in[3];
    const float* Wq      = (const float*)d_in[4];
    const float* Wk      = (const float*)d_in[5];
    const float* Wvp     = (const float*)d_in[6];
    const float* Wvq     = (const float*)d_in[7];
    const float* Wop     = (const float*)d_in[8];
    const float* bop     = (const float*)d_in[9];
    const float* Woq     = (const float*)d_in[10];
    const float* boq     = (const float*)d_in[11];
    const float* lng     = (const float*)d_in[12];
    const float* lnb     = (const float*)d_in[13];

    float* out = (float*)d_out;
    float* out_prot = out;                                   // (16,128,768)
    float* out_pep  = out + (long)BATCH * N_PEP * INNER;     // (16,2048,768)
    float* attn     = out_pep + (long)BATCH * M_PRO * INNER; // (16,8,128,2048)

    float *q, *k, *vp, *vq, *cp, *cq, *y1, *y2, *part;
    cudaGetSymbolAddress((void**)&q,  g_q);
    cudaGetSymbolAddress((void**)&k,  g_k);
    cudaGetSymbolAddress((void**)&vp, g_vp);
    cudaGetSymbolAddress((void**)&vq, g_vq);
    cudaGetSymbolAddress((void**)&cp, g_cp);
    cudaGetSymbolAddress((void**)&cq, g_cq);
    cudaGetSymbolAddress((void**)&y1, g_y1);
    cudaGetSymbolAddress((void**)&y2, g_y2);
    cudaGetSymbolAddress((void**)&part, g_part);

    const dim3 blk(256);

    // all four projections in one launch
    k_proj_all<<<dim3(6, 544), blk>>>(peptide, protein, Wq, Wvq, Wk, Wvp,
                                      q, vq, k, vp);

    // attention scores (mask fused) + softmax (attn lives in d_out)
    k_scores <<<dim3(16, 1, BATCH * HEADS), blk>>>(q, k, attn, pmask, promask);
    k_softmax<<<BATCH * HEADS * N_PEP, 256>>>(attn);

    // both context GEMMs in one launch (TRIM + UNR3R2)
    k_ctx_all<<<dim3(1, 1, BATCH * HEADS * KSPLIT + BATCH * HEADS * 16), blk>>>(
        attn, vp, vq, part, cq);
    k_reduce4<<<(BATCH * N_PEP * INNER / 4 + 255) / 256, blk>>>(part, cp);

    // output projections (y2 + y1 fused into one launch)
    k_out_dual<<<dim3(6, 272), blk>>>(cq, Woq, y2, cp, Wop, y1);

    // bias + residual + layernorm (fused)
    k_ln_dual<<<BATCH * N_PEP + BATCH * M_PRO, 256>>>(
        y1, bop, peptide, out_prot, y2, boq, protein, out_pep, lng, lnb);
}